// round 11
// baseline (speedup 1.0000x reference)
#include <cuda_runtime.h>
#include <cuda_fp16.h>
#include <math.h>
#include <cstdint>

// Problem shape (fixed)
#define NB 16
#define TT 1024
#define TS 1024
#define HH 1024
#define OO 1024

// ---------------------------------------------------------------------------
// Scratch (device globals; no allocation). _h/_l = exact fp16 hi/lo pairs.
// ---------------------------------------------------------------------------
__device__ __half g_hs_h  [(size_t)NB * TS * HH];
__device__ __half g_hs_l  [(size_t)NB * TS * HH];
__device__ __half g_ht_h  [(size_t)NB * TT * HH];
__device__ __half g_WaT_h [(size_t)HH * HH];        // scaled by 32
__device__ __half g_WaT_l [(size_t)HH * HH];        // scaled by 32
__device__ __half g_proj_h[(size_t)NB * TS * HH];
__device__ __half g_proj_l[(size_t)NB * TS * HH];
__device__ __half g_c_h   [(size_t)NB * TT * HH];   // c fp16 (from fused attend)
__device__ __half g_WcT_h [(size_t)OO * 2 * HH];    // [O=1024][K=2048] fp16
__device__ float  g_score [(size_t)NB * TT * TS];   // approx scores fp32
__device__ int    g_lens  [NB];

// ---------------------------------------------------------------------------
// Helpers / PTX (base ISA only)
// ---------------------------------------------------------------------------
__device__ __forceinline__ uint32_t smem_u32(const void* p) {
    uint32_t a;
    asm("{ .reg .u64 t; cvta.to.shared.u64 t, %1; cvt.u32.u64 %0, t; }"
        : "=r"(a) : "l"(p));
    return a;
}

#define CPASYNC16(saddr, gaddr) \
    asm volatile("cp.async.cg.shared.global [%0], [%1], 16;" :: "r"(saddr), "l"(gaddr))

__device__ __forceinline__ void ldm4(uint32_t* r, uint32_t addr) {
    asm volatile("ldmatrix.sync.aligned.m8n8.x4.shared.b16 {%0,%1,%2,%3}, [%4];"
                 : "=r"(r[0]), "=r"(r[1]), "=r"(r[2]), "=r"(r[3]) : "r"(addr));
}
__device__ __forceinline__ void mma16h(float* c, const uint32_t* a, const uint32_t* b) {
    asm volatile(
        "mma.sync.aligned.m16n8k16.row.col.f32.f16.f16.f32 "
        "{%0,%1,%2,%3}, {%4,%5,%6,%7}, {%8,%9}, {%0,%1,%2,%3};"
        : "+f"(c[0]), "+f"(c[1]), "+f"(c[2]), "+f"(c[3])
        : "r"(a[0]), "r"(a[1]), "r"(a[2]), "r"(a[3]), "r"(b[0]), "r"(b[1]));
}

struct SegArgsH { const __half* a[3]; const __half* b[3]; };

static const int NSTG = 3;                       // 3 stages -> 2 CTAs/SM
static const int STAGE = 32768;                  // 16KB A + 16KB B
static const int GEMM_SMEM = 1024 + NSTG * STAGE;

// ---------------------------------------------------------------------------
// fp16 GEMM: C[M,N] = sum_seg A_seg[M,1024] * B_seg[N,1024]^T (fp16 in, fp32 acc)
// CTA tile 128x128, k-step 64, 8 warps (2x4) with 64x32 warp tiles,
// 3-stage cp.async pipeline, SW128 xor swizzle, ldmatrix fragments.
// EPI: 0 fp32 out, 1 fp16 split out (scaled), 2 tanh(x+bias) fp32
// ---------------------------------------------------------------------------
template <int EPI, int NSEG>
__global__ __launch_bounds__(256, 2)
void gemm_fp16(const SegArgsH segs, float* __restrict__ Cf,
               __half* __restrict__ Ch, __half* __restrict__ Ch2,
               const float* __restrict__ bias, float oscale,
               int ldb, int ldc, long long sA, long long sB, long long sC)
{
    extern __shared__ char smem[];
    const uint32_t data = (smem_u32(smem) + 1023) & ~1023u;

    const int tid  = threadIdx.x;
    const int lane = tid & 31;
    const int warp = tid >> 5;
    const int wm = (warp >> 2) << 6;
    const int wn = (warp & 3) << 5;
    const int bm = blockIdx.y << 7;
    const int bn = blockIdx.x << 7;

    const long long zA = (long long)blockIdx.z * sA;
    const long long zB = (long long)blockIdx.z * sB;

    const int KT = NSEG * 16;            // k-steps of 64 fp16

    auto fill = [&](int kt, int s) {
        const int seg = kt >> 4;
        const int ka  = (kt & 15) << 6;
        const __half* Ap = segs.a[seg] + zA;
        const __half* Bp = segs.b[seg] + zB;
        const uint32_t sa = data + s * STAGE;
        const uint32_t sb = sa + 16384;
#pragma unroll
        for (int i = 0; i < 4; i++) {
            int c = tid + (i << 8);
            int row = c >> 3, ch = c & 7;
            const __half* g = Ap + (size_t)(bm + row) * 1024 + ka + (ch << 3);
            CPASYNC16(sa + (row << 7) + (((ch ^ (row & 7))) << 4), g);
        }
#pragma unroll
        for (int i = 0; i < 4; i++) {
            int c = tid + (i << 8);
            int row = c >> 3, ch = c & 7;
            const __half* g = Bp + (size_t)(bn + row) * ldb + ka + (ch << 3);
            CPASYNC16(sb + (row << 7) + (((ch ^ (row & 7))) << 4), g);
        }
    };

    fill(0, 0);
    asm volatile("cp.async.commit_group;" ::: "memory");
    fill(1, 1);
    asm volatile("cp.async.commit_group;" ::: "memory");

    float acc[4][4][4];
#pragma unroll
    for (int a = 0; a < 4; a++)
#pragma unroll
        for (int b = 0; b < 4; b++)
#pragma unroll
            for (int c = 0; c < 4; c++) acc[a][b][c] = 0.f;

    const int r8   = lane & 7;
    const int tile = lane >> 3;
    const int amo  = (tile & 1) << 3;
    const int akc  = tile >> 1;
    const int bno  = (lane >> 4) << 3;
    const int bkc  = (lane >> 3) & 1;

    int sc = 0;
    for (int kt = 0; kt < KT; kt++) {
        asm volatile("cp.async.wait_group 1;" ::: "memory");
        __syncthreads();

        int nf = kt + 2;
        int fs = (sc == 0) ? 2 : sc - 1;
        if (nf < KT) fill(nf, fs);
        asm volatile("cp.async.commit_group;" ::: "memory");

        const uint32_t Ab = data + sc * STAGE;
        const uint32_t Bs = Ab + 16384;
#pragma unroll
        for (int k16 = 0; k16 < 4; k16++) {
            uint32_t af[4][4], bf[2][4];
#pragma unroll
            for (int mt = 0; mt < 4; mt++) {
                int arow = wm + mt * 16 + r8 + amo;
                int achk = 2 * k16 + akc;
                ldm4(af[mt], Ab + (arow << 7) + (((achk ^ (arow & 7))) << 4));
            }
#pragma unroll
            for (int p = 0; p < 2; p++) {
                int brow = wn + (p << 4) + r8 + bno;
                int bchk = 2 * k16 + bkc;
                ldm4(bf[p], Bs + (brow << 7) + (((bchk ^ (brow & 7))) << 4));
            }
#pragma unroll
            for (int mt = 0; mt < 4; mt++)
#pragma unroll
                for (int nt = 0; nt < 4; nt++)
                    mma16h(acc[mt][nt], af[mt], &bf[nt >> 1][(nt & 1) << 1]);
        }
        sc = (sc == 2) ? 0 : sc + 1;
    }

    const int row0 = bm + wm + (lane >> 2);
    const int col0 = bn + wn + ((lane & 3) << 1);
#pragma unroll
    for (int mt = 0; mt < 4; mt++) {
#pragma unroll
        for (int nt = 0; nt < 4; nt++) {
            int col = col0 + nt * 8;
#pragma unroll
            for (int h = 0; h < 2; h++) {
                int row = row0 + mt * 16 + h * 8;
                float v0 = acc[mt][nt][2 * h + 0];
                float v1 = acc[mt][nt][2 * h + 1];
                size_t off = (size_t)blockIdx.z * sC + (size_t)row * ldc + col;
                if (EPI == 0) {
                    float2 o = {v0, v1};
                    *(float2*)(Cf + off) = o;
                } else if (EPI == 1) {          // scaled fp16 split
                    v0 *= oscale; v1 *= oscale;
                    __half h0 = __float2half_rn(v0);
                    __half h1 = __float2half_rn(v1);
                    __half2 hv; hv.x = h0; hv.y = h1;
                    __half2 lv;
                    lv.x = __float2half_rn(v0 - __half2float(h0));
                    lv.y = __float2half_rn(v1 - __half2float(h1));
                    *(__half2*)(Ch + off)  = hv;
                    *(__half2*)(Ch2 + off) = lv;
                } else {                        // EPI == 2: tanh + bias
                    float2 o = {tanhf(v0 + bias[col]), tanhf(v1 + bias[col + 1])};
                    *(float2*)(Cf + off) = o;
                }
            }
        }
    }
}

// ---------------------------------------------------------------------------
// Preprocessing
// ---------------------------------------------------------------------------
// x -> fp16 hi/lo pairs (row-major)
__global__ void prep_split(const float* __restrict__ in, __half* __restrict__ hh,
                           __half* __restrict__ hl, size_t n4)
{
    size_t i  = (size_t)blockIdx.x * blockDim.x + threadIdx.x;
    size_t st = (size_t)gridDim.x * blockDim.x;
    for (; i < n4; i += st) {
        float4 v = ((const float4*)in)[i];
        __half2 h0, h1, l0, l1;
        h0.x = __float2half_rn(v.x); l0.x = __float2half_rn(v.x - __half2float(h0.x));
        h0.y = __float2half_rn(v.y); l0.y = __float2half_rn(v.y - __half2float(h0.y));
        h1.x = __float2half_rn(v.z); l1.x = __float2half_rn(v.z - __half2float(h1.x));
        h1.y = __float2half_rn(v.w); l1.y = __float2half_rn(v.w - __half2float(h1.y));
        ((__half2*)hh)[2 * i]     = h0;
        ((__half2*)hh)[2 * i + 1] = h1;
        ((__half2*)hl)[2 * i]     = l0;
        ((__half2*)hl)[2 * i + 1] = l1;
    }
}

// x -> fp16 (single, row-major)
__global__ void prep_half(const float* __restrict__ in, __half* __restrict__ out,
                          size_t n4)
{
    size_t i  = (size_t)blockIdx.x * blockDim.x + threadIdx.x;
    size_t st = (size_t)gridDim.x * blockDim.x;
    for (; i < n4; i += st) {
        float4 v = ((const float4*)in)[i];
        __half2 h0, h1;
        h0.x = __float2half_rn(v.x); h0.y = __float2half_rn(v.y);
        h1.x = __float2half_rn(v.z); h1.y = __float2half_rn(v.w);
        ((__half2*)out)[2 * i]     = h0;
        ((__half2*)out)[2 * i + 1] = h1;
    }
}

// Merged weight prep: blockIdx.y < 32 -> Wa (fp16 split, scaled 32, transpose);
// else -> Wc (fp16 single, transpose).
__global__ void prep_w(const float* __restrict__ Wa, const float* __restrict__ Wc,
                       __half* __restrict__ WaT_h, __half* __restrict__ WaT_l,
                       __half* __restrict__ WcT_h)
{
    __shared__ float t[32][33];
    int y = blockIdx.y;
    bool isWa = (y < 32);
    const float* src = isWa ? Wa : Wc;
    int r0 = (isWa ? y : (y - 32)) << 5;
    int c0 = blockIdx.x << 5;
    int tx = threadIdx.x, ty = threadIdx.y;
#pragma unroll
    for (int i = 0; i < 32; i += 8)
        t[ty + i][tx] = src[(size_t)(r0 + ty + i) * 1024 + c0 + tx];
    __syncthreads();
    if (isWa) {
#pragma unroll
        for (int i = 0; i < 32; i += 8) {
            float v = 32.0f * t[tx][ty + i];
            __half h = __float2half_rn(v);
            __half l = __float2half_rn(v - __half2float(h));
            size_t idx = (size_t)(c0 + ty + i) * 1024 + r0 + tx;
            WaT_h[idx] = h;
            WaT_l[idx] = l;
        }
    } else {
#pragma unroll
        for (int i = 0; i < 32; i += 8) {
            size_t idx = (size_t)(c0 + ty + i) * 2048 + r0 + tx;
            WcT_h[idx] = __float2half_rn(t[tx][ty + i]);
        }
    }
}

__global__ void lens_kernel(const int* __restrict__ source, int* __restrict__ lens)
{
    int b = blockIdx.x, tid = threadIdx.x;
    int cnt = 0;
    for (int s = tid; s < TS; s += blockDim.x)
        cnt += (source[(size_t)b * TS + s] != 0);
    __shared__ int red[256];
    red[tid] = cnt;
    __syncthreads();
    for (int s = 128; s > 0; s >>= 1) {
        if (tid < s) red[tid] += red[tid + s];
        __syncthreads();
    }
    if (tid == 0) lens[b] = red[0];
}

// ---------------------------------------------------------------------------
// Fused attend: warp-per-row. Select candidates from approx scores
// (margin-padded cutoff), recompute exactly (fp32 ht . (proj_h+proj_l)),
// softmax, then gather c[row,:] = sum a_k * hs[b,s_k,:] -> fp16.
// No block barriers, no atomics, no sparse-list gmem round-trip.
// ---------------------------------------------------------------------------
#define CAP 192
__global__ __launch_bounds__(256)
void attend(const float* __restrict__ score, const float* __restrict__ ht,
            const __half* __restrict__ proj_h, const __half* __restrict__ proj_l,
            const float* __restrict__ hs, __half* __restrict__ c_h,
            const int* __restrict__ lens)
{
    __shared__ int   s_idx[8][CAP];
    __shared__ float s_sc [8][CAP];
    const int w    = threadIdx.x >> 5;
    const int lane = threadIdx.x & 31;
    const int row  = (blockIdx.x << 3) + w;
    const int b    = row >> 10;
    const int len  = lens[b];
    const float* srow = score + (size_t)row * TS;

    // pass 1: masked warp-max of approx scores (row cached in registers)
    float4 sv[8];
    float m = -1e30f;
#pragma unroll
    for (int i = 0; i < 8; i++) {
        sv[i] = ((const float4*)srow)[lane + (i << 5)];
        int base = (lane + (i << 5)) << 2;
        if (base + 0 < len) m = fmaxf(m, sv[i].x);
        if (base + 1 < len) m = fmaxf(m, sv[i].y);
        if (base + 2 < len) m = fmaxf(m, sv[i].z);
        if (base + 3 < len) m = fmaxf(m, sv[i].w);
    }
#pragma unroll
    for (int s = 16; s > 0; s >>= 1)
        m = fmaxf(m, __shfl_xor_sync(0xffffffffu, m, s));
    const float thr = m - 18.2f;          // 17.33 true cutoff + approx-err margin

    // pass 2: ballot-compact candidates into per-warp smem list
    int cnt = 0;
#pragma unroll
    for (int i = 0; i < 8; i++) {
        int base = (lane + (i << 5)) << 2;
        float v[4] = {sv[i].x, sv[i].y, sv[i].z, sv[i].w};
#pragma unroll
        for (int j = 0; j < 4; j++) {
            bool p = (base + j < len) && (v[j] >= thr);
            unsigned mk = __ballot_sync(0xffffffffu, p);
            if (p) {
                int pos = cnt + __popc(mk & ((1u << lane) - 1));
                if (pos < CAP) s_idx[w][pos] = base + j;
            }
            cnt += __popc(mk);
        }
    }
    if (cnt > CAP) cnt = CAP;
    __syncwarp();

    // ht row (fp32 exact) into registers: lane holds k = j*32+lane
    float htr[32];
#pragma unroll
    for (int j = 0; j < 32; j++)
        htr[j] = ht[(size_t)row * HH + (j << 5) + lane];

    // pass 3: exact rescore (warp-collective dot per candidate)
    for (int ci = 0; ci < cnt; ci++) {
        int s = s_idx[w][ci];
        const __half* ph = proj_h + ((size_t)b * TS + s) * HH;
        const __half* pl = proj_l + ((size_t)b * TS + s) * HH;
        float acc = 0.f;
#pragma unroll
        for (int j = 0; j < 32; j++) {
            int k = (j << 5) + lane;
            acc = fmaf(htr[j], __half2float(ph[k]) + __half2float(pl[k]), acc);
        }
#pragma unroll
        for (int s2 = 16; s2 > 0; s2 >>= 1)
            acc += __shfl_xor_sync(0xffffffffu, acc, s2);
        if (lane == 0) s_sc[w][ci] = acc;
    }
    __syncwarp();

    // pass 4: softmax over candidates (in-warp)
    float mx = -1e30f;
    for (int i = lane; i < cnt; i += 32) mx = fmaxf(mx, s_sc[w][i]);
#pragma unroll
    for (int s = 16; s > 0; s >>= 1)
        mx = fmaxf(mx, __shfl_xor_sync(0xffffffffu, mx, s));
    float sum = 0.f;
    for (int i = lane; i < cnt; i += 32) {
        float e = expf(s_sc[w][i] - mx);
        s_sc[w][i] = e;
        sum += e;
    }
#pragma unroll
    for (int s = 16; s > 0; s >>= 1)
        sum += __shfl_xor_sync(0xffffffffu, sum, s);
    const float inv = 1.0f / sum;
    __syncwarp();

    // pass 5: gather c = sum a_k * hs[s_k]  (fp32 accum in registers)
    float acc2[32];
#pragma unroll
    for (int j = 0; j < 32; j++) acc2[j] = 0.f;
    for (int ci = 0; ci < cnt; ci++) {
        float wgt = s_sc[w][ci] * inv;
        const float* hr = hs + ((size_t)b * TS + s_idx[w][ci]) * HH;
#pragma unroll
        for (int j = 0; j < 32; j++)
            acc2[j] = fmaf(wgt, hr[(j << 5) + lane], acc2[j]);
    }
    __half* crow = c_h + (size_t)row * HH;
#pragma unroll
    for (int j = 0; j < 32; j++)
        crow[(j << 5) + lane] = __float2half_rn(acc2[j]);
}

// ---------------------------------------------------------------------------
// Host launch
// ---------------------------------------------------------------------------
extern "C" void kernel_launch(void* const* d_in, const int* in_sizes, int n_in,
                              void* d_out, int out_size)
{
    const float* ht     = (const float*)d_in[0];
    const float* hs     = (const float*)d_in[1];
    const float* W_a    = (const float*)d_in[2];
    const float* W_c    = (const float*)d_in[3];
    const float* bias   = (const float*)d_in[4];
    const int*   source = (const int*)d_in[5];
    float* out = (float*)d_out;

    __half *hs_h, *hs_l, *ht_h, *WaT_h, *WaT_l, *proj_h, *proj_l, *c_h, *WcT_h;
    float* score;
    int* lens;
    cudaGetSymbolAddress((void**)&hs_h,   g_hs_h);
    cudaGetSymbolAddress((void**)&hs_l,   g_hs_l);
    cudaGetSymbolAddress((void**)&ht_h,   g_ht_h);
    cudaGetSymbolAddress((void**)&WaT_h,  g_WaT_h);
    cudaGetSymbolAddress((void**)&WaT_l,  g_WaT_l);
    cudaGetSymbolAddress((void**)&proj_h, g_proj_h);
    cudaGetSymbolAddress((void**)&proj_l, g_proj_l);
    cudaGetSymbolAddress((void**)&c_h,    g_c_h);
    cudaGetSymbolAddress((void**)&WcT_h,  g_WcT_h);
    cudaGetSymbolAddress((void**)&score,  g_score);
    cudaGetSymbolAddress((void**)&lens,   g_lens);

    cudaFuncSetAttribute(gemm_fp16<1,3>, cudaFuncAttributeMaxDynamicSharedMemorySize, GEMM_SMEM);
    cudaFuncSetAttribute(gemm_fp16<0,1>, cudaFuncAttributeMaxDynamicSharedMemorySize, GEMM_SMEM);
    cudaFuncSetAttribute(gemm_fp16<2,2>, cudaFuncAttributeMaxDynamicSharedMemorySize, GEMM_SMEM);

    // Preprocess
    lens_kernel<<<NB, 256>>>(source, lens);
    prep_w<<<dim3(32, 96), dim3(32, 8)>>>(W_a, W_c, WaT_h, WaT_l, WcT_h);
    prep_half<<<2048, 256>>>(ht, ht_h, (size_t)NB * TT * HH / 4);
    prep_split<<<2048, 256>>>(hs, hs_h, hs_l, (size_t)NB * TS * HH / 4);

    // G1: proj = hs @ W_a  (3xFP16, Wa scaled by 32) -> proj_h, proj_l (x 1/32)
    {
        SegArgsH s{};
        s.a[0] = hs_h;  s.a[1] = hs_l;  s.a[2] = hs_h;
        s.b[0] = WaT_h; s.b[1] = WaT_h; s.b[2] = WaT_l;
        gemm_fp16<1,3><<<dim3(HH/128, NB*TS/128, 1), 256, GEMM_SMEM>>>(
            s, nullptr, proj_h, proj_l, nullptr, 1.0f / 32.0f,
            1024, HH, 0, 0, (long long)TT * HH);
    }

    // G2 (approx): score[b] = ht_h[b] @ proj_h[b]^T  (single fp16), fp32 out
    {
        SegArgsH s{};
        s.a[0] = ht_h;
        s.b[0] = proj_h;
        gemm_fp16<0,1><<<dim3(TS/128, TT/128, NB), 256, GEMM_SMEM>>>(
            s, score, nullptr, nullptr, nullptr, 1.0f,
            1024, TS, (long long)TT * HH, (long long)TS * HH, (long long)TT * TS);
    }

    // Fused: select + exact rescore + softmax + sparse AV -> c_h
    attend<<<NB * TT / 8, 256>>>(score, ht, proj_h, proj_l, hs, c_h, lens);

    // G4: out = tanh([c|ht] @ W_c + b)  (single fp16, 2 segments over K=2048)
    {
        SegArgsH s{};
        s.a[0] = c_h;   s.a[1] = ht_h;
        s.b[0] = WcT_h; s.b[1] = WcT_h + 1024;
        gemm_fp16<2,2><<<dim3(OO/128, NB*TT/128, 1), 256, GEMM_SMEM>>>(
            s, out, nullptr, nullptr, bias, 1.0f,
            2048, OO, 0, 0, 0);
    }
}

// round 12
// speedup vs baseline: 1.1070x; 1.1070x over previous
#include <cuda_runtime.h>
#include <cuda_fp16.h>
#include <math.h>
#include <cstdint>

// Problem shape (fixed)
#define NB 16
#define TT 1024
#define TS 1024
#define HH 1024
#define OO 1024

// ---------------------------------------------------------------------------
// Scratch (device globals; no allocation). _h/_l = exact fp16 hi/lo pairs.
// ---------------------------------------------------------------------------
__device__ __half g_hs_h  [(size_t)NB * TS * HH];
__device__ __half g_hs_l  [(size_t)NB * TS * HH];
__device__ __half g_ht_h  [(size_t)NB * TT * HH];
__device__ __half g_WaT_h [(size_t)HH * HH];        // scaled by 32
__device__ __half g_WaT_l [(size_t)HH * HH];        // scaled by 32
__device__ __half g_proj_h[(size_t)NB * TS * HH];
__device__ __half g_proj_l[(size_t)NB * TS * HH];
__device__ __half g_c_h   [(size_t)NB * TT * HH];   // c fp16
__device__ __half g_WcT_h [(size_t)OO * 2 * HH];    // [O=1024][K=2048] fp16
__device__ __half g_score [(size_t)NB * TT * TS];   // approx scores fp16
__device__ int    g_lens  [NB];

// ---------------------------------------------------------------------------
// Helpers / PTX (base ISA only)
// ---------------------------------------------------------------------------
__device__ __forceinline__ uint32_t smem_u32(const void* p) {
    uint32_t a;
    asm("{ .reg .u64 t; cvta.to.shared.u64 t, %1; cvt.u32.u64 %0, t; }"
        : "=r"(a) : "l"(p));
    return a;
}

#define CPASYNC16(saddr, gaddr) \
    asm volatile("cp.async.cg.shared.global [%0], [%1], 16;" :: "r"(saddr), "l"(gaddr))

__device__ __forceinline__ void ldm4(uint32_t* r, uint32_t addr) {
    asm volatile("ldmatrix.sync.aligned.m8n8.x4.shared.b16 {%0,%1,%2,%3}, [%4];"
                 : "=r"(r[0]), "=r"(r[1]), "=r"(r[2]), "=r"(r[3]) : "r"(addr));
}
__device__ __forceinline__ void mma16h(float* c, const uint32_t* a, const uint32_t* b) {
    asm volatile(
        "mma.sync.aligned.m16n8k16.row.col.f32.f16.f16.f32 "
        "{%0,%1,%2,%3}, {%4,%5,%6,%7}, {%8,%9}, {%0,%1,%2,%3};"
        : "+f"(c[0]), "+f"(c[1]), "+f"(c[2]), "+f"(c[3])
        : "r"(a[0]), "r"(a[1]), "r"(a[2]), "r"(a[3]), "r"(b[0]), "r"(b[1]));
}

struct SegArgsH { const __half* a[3]; const __half* b[3]; };

static const int NSTG = 3;                       // 3 stages -> 2 CTAs/SM
static const int STAGE = 32768;                  // 16KB A + 16KB B
static const int GEMM_SMEM = 1024 + NSTG * STAGE;

// ---------------------------------------------------------------------------
// fp16 GEMM: C[M,N] = sum_seg A_seg[M,1024] * B_seg[N,1024]^T (fp16 in, fp32 acc)
// EPI: 1 fp16 split out (scaled), 2 tanh(x+bias) fp32, 3 fp16 single out
// ---------------------------------------------------------------------------
template <int EPI, int NSEG>
__global__ __launch_bounds__(256, 2)
void gemm_fp16(const SegArgsH segs, float* __restrict__ Cf,
               __half* __restrict__ Ch, __half* __restrict__ Ch2,
               const float* __restrict__ bias, float oscale,
               int ldb, int ldc, long long sA, long long sB, long long sC)
{
    extern __shared__ char smem[];
    const uint32_t data = (smem_u32(smem) + 1023) & ~1023u;

    const int tid  = threadIdx.x;
    const int lane = tid & 31;
    const int warp = tid >> 5;
    const int wm = (warp >> 2) << 6;
    const int wn = (warp & 3) << 5;
    const int bm = blockIdx.y << 7;
    const int bn = blockIdx.x << 7;

    const long long zA = (long long)blockIdx.z * sA;
    const long long zB = (long long)blockIdx.z * sB;

    const int KT = NSEG * 16;            // k-steps of 64 fp16

    auto fill = [&](int kt, int s) {
        const int seg = kt >> 4;
        const int ka  = (kt & 15) << 6;
        const __half* Ap = segs.a[seg] + zA;
        const __half* Bp = segs.b[seg] + zB;
        const uint32_t sa = data + s * STAGE;
        const uint32_t sb = sa + 16384;
#pragma unroll
        for (int i = 0; i < 4; i++) {
            int c = tid + (i << 8);
            int row = c >> 3, ch = c & 7;
            const __half* g = Ap + (size_t)(bm + row) * 1024 + ka + (ch << 3);
            CPASYNC16(sa + (row << 7) + (((ch ^ (row & 7))) << 4), g);
        }
#pragma unroll
        for (int i = 0; i < 4; i++) {
            int c = tid + (i << 8);
            int row = c >> 3, ch = c & 7;
            const __half* g = Bp + (size_t)(bn + row) * ldb + ka + (ch << 3);
            CPASYNC16(sb + (row << 7) + (((ch ^ (row & 7))) << 4), g);
        }
    };

    fill(0, 0);
    asm volatile("cp.async.commit_group;" ::: "memory");
    fill(1, 1);
    asm volatile("cp.async.commit_group;" ::: "memory");

    float acc[4][4][4];
#pragma unroll
    for (int a = 0; a < 4; a++)
#pragma unroll
        for (int b = 0; b < 4; b++)
#pragma unroll
            for (int c = 0; c < 4; c++) acc[a][b][c] = 0.f;

    const int r8   = lane & 7;
    const int tile = lane >> 3;
    const int amo  = (tile & 1) << 3;
    const int akc  = tile >> 1;
    const int bno  = (lane >> 4) << 3;
    const int bkc  = (lane >> 3) & 1;

    int sc = 0;
    for (int kt = 0; kt < KT; kt++) {
        asm volatile("cp.async.wait_group 1;" ::: "memory");
        __syncthreads();

        int nf = kt + 2;
        int fs = (sc == 0) ? 2 : sc - 1;
        if (nf < KT) fill(nf, fs);
        asm volatile("cp.async.commit_group;" ::: "memory");

        const uint32_t Ab = data + sc * STAGE;
        const uint32_t Bs = Ab + 16384;
#pragma unroll
        for (int k16 = 0; k16 < 4; k16++) {
            uint32_t af[4][4], bf[2][4];
#pragma unroll
            for (int mt = 0; mt < 4; mt++) {
                int arow = wm + mt * 16 + r8 + amo;
                int achk = 2 * k16 + akc;
                ldm4(af[mt], Ab + (arow << 7) + (((achk ^ (arow & 7))) << 4));
            }
#pragma unroll
            for (int p = 0; p < 2; p++) {
                int brow = wn + (p << 4) + r8 + bno;
                int bchk = 2 * k16 + bkc;
                ldm4(bf[p], Bs + (brow << 7) + (((bchk ^ (brow & 7))) << 4));
            }
#pragma unroll
            for (int mt = 0; mt < 4; mt++)
#pragma unroll
                for (int nt = 0; nt < 4; nt++)
                    mma16h(acc[mt][nt], af[mt], &bf[nt >> 1][(nt & 1) << 1]);
        }
        sc = (sc == 2) ? 0 : sc + 1;
    }

    const int row0 = bm + wm + (lane >> 2);
    const int col0 = bn + wn + ((lane & 3) << 1);
#pragma unroll
    for (int mt = 0; mt < 4; mt++) {
#pragma unroll
        for (int nt = 0; nt < 4; nt++) {
            int col = col0 + nt * 8;
#pragma unroll
            for (int h = 0; h < 2; h++) {
                int row = row0 + mt * 16 + h * 8;
                float v0 = acc[mt][nt][2 * h + 0];
                float v1 = acc[mt][nt][2 * h + 1];
                size_t off = (size_t)blockIdx.z * sC + (size_t)row * ldc + col;
                if (EPI == 1) {                 // scaled fp16 split
                    v0 *= oscale; v1 *= oscale;
                    __half h0 = __float2half_rn(v0);
                    __half h1 = __float2half_rn(v1);
                    __half2 hv; hv.x = h0; hv.y = h1;
                    __half2 lv;
                    lv.x = __float2half_rn(v0 - __half2float(h0));
                    lv.y = __float2half_rn(v1 - __half2float(h1));
                    *(__half2*)(Ch + off)  = hv;
                    *(__half2*)(Ch2 + off) = lv;
                } else if (EPI == 2) {          // tanh + bias -> fp32
                    float2 o = {tanhf(v0 + bias[col]), tanhf(v1 + bias[col + 1])};
                    *(float2*)(Cf + off) = o;
                } else {                        // EPI == 3: fp16 single
                    __half2 hv;
                    hv.x = __float2half_rn(v0);
                    hv.y = __float2half_rn(v1);
                    *(__half2*)(Ch + off) = hv;
                }
            }
        }
    }
}

// ---------------------------------------------------------------------------
// Preprocessing
// ---------------------------------------------------------------------------
__global__ void prep_split(const float* __restrict__ in, __half* __restrict__ hh,
                           __half* __restrict__ hl, size_t n4)
{
    size_t i  = (size_t)blockIdx.x * blockDim.x + threadIdx.x;
    size_t st = (size_t)gridDim.x * blockDim.x;
    for (; i < n4; i += st) {
        float4 v = ((const float4*)in)[i];
        __half2 h0, h1, l0, l1;
        h0.x = __float2half_rn(v.x); l0.x = __float2half_rn(v.x - __half2float(h0.x));
        h0.y = __float2half_rn(v.y); l0.y = __float2half_rn(v.y - __half2float(h0.y));
        h1.x = __float2half_rn(v.z); l1.x = __float2half_rn(v.z - __half2float(h1.x));
        h1.y = __float2half_rn(v.w); l1.y = __float2half_rn(v.w - __half2float(h1.y));
        ((__half2*)hh)[2 * i]     = h0;
        ((__half2*)hh)[2 * i + 1] = h1;
        ((__half2*)hl)[2 * i]     = l0;
        ((__half2*)hl)[2 * i + 1] = l1;
    }
}

__global__ void prep_half(const float* __restrict__ in, __half* __restrict__ out,
                          size_t n4)
{
    size_t i  = (size_t)blockIdx.x * blockDim.x + threadIdx.x;
    size_t st = (size_t)gridDim.x * blockDim.x;
    for (; i < n4; i += st) {
        float4 v = ((const float4*)in)[i];
        __half2 h0, h1;
        h0.x = __float2half_rn(v.x); h0.y = __float2half_rn(v.y);
        h1.x = __float2half_rn(v.z); h1.y = __float2half_rn(v.w);
        ((__half2*)out)[2 * i]     = h0;
        ((__half2*)out)[2 * i + 1] = h1;
    }
}

// Merged weight prep: blockIdx.y < 32 -> Wa (fp16 split, scaled 32, transpose);
// else -> Wc (fp16 single, transpose).
__global__ void prep_w(const float* __restrict__ Wa, const float* __restrict__ Wc,
                       __half* __restrict__ WaT_h, __half* __restrict__ WaT_l,
                       __half* __restrict__ WcT_h)
{
    __shared__ float t[32][33];
    int y = blockIdx.y;
    bool isWa = (y < 32);
    const float* src = isWa ? Wa : Wc;
    int r0 = (isWa ? y : (y - 32)) << 5;
    int c0 = blockIdx.x << 5;
    int tx = threadIdx.x, ty = threadIdx.y;
#pragma unroll
    for (int i = 0; i < 32; i += 8)
        t[ty + i][tx] = src[(size_t)(r0 + ty + i) * 1024 + c0 + tx];
    __syncthreads();
    if (isWa) {
#pragma unroll
        for (int i = 0; i < 32; i += 8) {
            float v = 32.0f * t[tx][ty + i];
            __half h = __float2half_rn(v);
            __half l = __float2half_rn(v - __half2float(h));
            size_t idx = (size_t)(c0 + ty + i) * 1024 + r0 + tx;
            WaT_h[idx] = h;
            WaT_l[idx] = l;
        }
    } else {
#pragma unroll
        for (int i = 0; i < 32; i += 8) {
            size_t idx = (size_t)(c0 + ty + i) * 2048 + r0 + tx;
            WcT_h[idx] = __float2half_rn(t[tx][ty + i]);
        }
    }
}

__global__ void lens_kernel(const int* __restrict__ source, int* __restrict__ lens)
{
    int b = blockIdx.x, tid = threadIdx.x;
    int cnt = 0;
    for (int s = tid; s < TS; s += blockDim.x)
        cnt += (source[(size_t)b * TS + s] != 0);
    __shared__ int red[256];
    red[tid] = cnt;
    __syncthreads();
    for (int s = 128; s > 0; s >>= 1) {
        if (tid < s) red[tid] += red[tid + s];
        __syncthreads();
    }
    if (tid == 0) lens[b] = red[0];
}

// ---------------------------------------------------------------------------
// Fused attend (block-per-row, low registers): select candidates from fp16
// approx scores (cutoff max-10: dropped weights < 4.5e-5, mass < ~1e-4),
// exact-rescore (fp32 ht . (proj_h+proj_l)), softmax, dense-thread gather
// c[row,:] = sum a_k hs[s_k,:] with float4 accumulators -> fp16.
// ---------------------------------------------------------------------------
#define CAP 64
__global__ __launch_bounds__(256)
void attend(const __half* __restrict__ score, const float* __restrict__ ht,
            const __half* __restrict__ proj_h, const __half* __restrict__ proj_l,
            const float* __restrict__ hs, __half* __restrict__ c_h,
            const int* __restrict__ lens)
{
    __shared__ float htrow[1024];
    __shared__ int   cand[CAP];
    __shared__ float exsc[CAP];
    __shared__ float wred[8];
    __shared__ int   ccnt;
    __shared__ float s_inv;

    const int row  = blockIdx.x;                 // 0 .. NB*TT-1
    const int b    = row >> 10;
    const int tid  = threadIdx.x;
    const int warp = tid >> 5, lane = tid & 31;
    const int len  = lens[b];
    const __half* srow = score + (size_t)row * TS;

    if (tid == 0) ccnt = 0;

    // ht row (fp32) into smem
    ((float4*)htrow)[tid] = ((const float4*)(ht + (size_t)row * HH))[tid];

    // load 4 fp16 scores per thread; masked max via shfl + cross-warp smem
    __half2 p0 = ((const __half2*)srow)[2 * tid];
    __half2 p1 = ((const __half2*)srow)[2 * tid + 1];
    float v0 = __half2float(p0.x), v1 = __half2float(p0.y);
    float v2 = __half2float(p1.x), v3 = __half2float(p1.y);
    int base = tid << 2;
    float m = -1e30f;
    if (base + 0 < len) m = fmaxf(m, v0);
    if (base + 1 < len) m = fmaxf(m, v1);
    if (base + 2 < len) m = fmaxf(m, v2);
    if (base + 3 < len) m = fmaxf(m, v3);
#pragma unroll
    for (int s = 16; s > 0; s >>= 1)
        m = fmaxf(m, __shfl_xor_sync(0xffffffffu, m, s));
    if (lane == 0) wred[warp] = m;
    __syncthreads();
    if (warp == 0) {
        float mm = (lane < 8) ? wred[lane] : -1e30f;
#pragma unroll
        for (int s = 4; s > 0; s >>= 1)
            mm = fmaxf(mm, __shfl_xor_sync(0xffffffffu, mm, s));
        if (lane == 0) wred[0] = mm;
    }
    __syncthreads();
    const float thr = wred[0] - 10.0f;           // 9.2 cutoff + margin

    // select candidates (few -> atomics cheap)
    if (base + 0 < len && v0 >= thr) { int p = atomicAdd(&ccnt, 1); if (p < CAP) cand[p] = base + 0; }
    if (base + 1 < len && v1 >= thr) { int p = atomicAdd(&ccnt, 1); if (p < CAP) cand[p] = base + 1; }
    if (base + 2 < len && v2 >= thr) { int p = atomicAdd(&ccnt, 1); if (p < CAP) cand[p] = base + 2; }
    if (base + 3 < len && v3 >= thr) { int p = atomicAdd(&ccnt, 1); if (p < CAP) cand[p] = base + 3; }
    __syncthreads();
    const int C = (ccnt < CAP) ? ccnt : CAP;

    // exact rescore: warp per candidate
    for (int ci = warp; ci < C; ci += 8) {
        int s = cand[ci];
        const __half* ph = proj_h + ((size_t)b * TS + s) * HH;
        const __half* pl = proj_l + ((size_t)b * TS + s) * HH;
        float acc = 0.f;
#pragma unroll
        for (int j = 0; j < 32; j++) {
            int k = (j << 5) + lane;
            acc = fmaf(htrow[k], __half2float(ph[k]) + __half2float(pl[k]), acc);
        }
#pragma unroll
        for (int s2 = 16; s2 > 0; s2 >>= 1)
            acc += __shfl_xor_sync(0xffffffffu, acc, s2);
        if (lane == 0) exsc[ci] = acc;
    }
    __syncthreads();

    // softmax over candidates (C tiny)
    if (tid == 0) {
        float mx = -1e30f;
        for (int i = 0; i < C; i++) mx = fmaxf(mx, exsc[i]);
        float sum = 0.f;
        for (int i = 0; i < C; i++) {
            float e = expf(exsc[i] - mx);
            exsc[i] = e;
            sum += e;
        }
        s_inv = 1.0f / sum;
    }
    __syncthreads();
    const float inv = s_inv;

    // gather: c = sum a_k * hs[s_k]  (float4 accumulator per thread)
    float4 acc4 = {0.f, 0.f, 0.f, 0.f};
    for (int ci = 0; ci < C; ci++) {
        float wgt = exsc[ci] * inv;
        float4 h = ((const float4*)(hs + ((size_t)b * TS + cand[ci]) * HH))[tid];
        acc4.x = fmaf(wgt, h.x, acc4.x);
        acc4.y = fmaf(wgt, h.y, acc4.y);
        acc4.z = fmaf(wgt, h.z, acc4.z);
        acc4.w = fmaf(wgt, h.w, acc4.w);
    }
    __half2 o0, o1;
    o0.x = __float2half_rn(acc4.x); o0.y = __float2half_rn(acc4.y);
    o1.x = __float2half_rn(acc4.z); o1.y = __float2half_rn(acc4.w);
    ((__half2*)(c_h + (size_t)row * HH))[2 * tid]     = o0;
    ((__half2*)(c_h + (size_t)row * HH))[2 * tid + 1] = o1;
}

// ---------------------------------------------------------------------------
// Host launch
// ---------------------------------------------------------------------------
extern "C" void kernel_launch(void* const* d_in, const int* in_sizes, int n_in,
                              void* d_out, int out_size)
{
    const float* ht     = (const float*)d_in[0];
    const float* hs     = (const float*)d_in[1];
    const float* W_a    = (const float*)d_in[2];
    const float* W_c    = (const float*)d_in[3];
    const float* bias   = (const float*)d_in[4];
    const int*   source = (const int*)d_in[5];
    float* out = (float*)d_out;

    __half *hs_h, *hs_l, *ht_h, *WaT_h, *WaT_l, *proj_h, *proj_l, *c_h, *WcT_h, *score;
    int* lens;
    cudaGetSymbolAddress((void**)&hs_h,   g_hs_h);
    cudaGetSymbolAddress((void**)&hs_l,   g_hs_l);
    cudaGetSymbolAddress((void**)&ht_h,   g_ht_h);
    cudaGetSymbolAddress((void**)&WaT_h,  g_WaT_h);
    cudaGetSymbolAddress((void**)&WaT_l,  g_WaT_l);
    cudaGetSymbolAddress((void**)&proj_h, g_proj_h);
    cudaGetSymbolAddress((void**)&proj_l, g_proj_l);
    cudaGetSymbolAddress((void**)&c_h,    g_c_h);
    cudaGetSymbolAddress((void**)&WcT_h,  g_WcT_h);
    cudaGetSymbolAddress((void**)&score,  g_score);
    cudaGetSymbolAddress((void**)&lens,   g_lens);

    cudaFuncSetAttribute(gemm_fp16<1,3>, cudaFuncAttributeMaxDynamicSharedMemorySize, GEMM_SMEM);
    cudaFuncSetAttribute(gemm_fp16<3,1>, cudaFuncAttributeMaxDynamicSharedMemorySize, GEMM_SMEM);
    cudaFuncSetAttribute(gemm_fp16<2,2>, cudaFuncAttributeMaxDynamicSharedMemorySize, GEMM_SMEM);

    // Preprocess
    lens_kernel<<<NB, 256>>>(source, lens);
    prep_w<<<dim3(32, 96), dim3(32, 8)>>>(W_a, W_c, WaT_h, WaT_l, WcT_h);
    prep_half<<<2048, 256>>>(ht, ht_h, (size_t)NB * TT * HH / 4);
    prep_split<<<2048, 256>>>(hs, hs_h, hs_l, (size_t)NB * TS * HH / 4);

    // G1: proj = hs @ W_a  (3xFP16, Wa scaled by 32) -> proj_h, proj_l (x 1/32)
    {
        SegArgsH s{};
        s.a[0] = hs_h;  s.a[1] = hs_l;  s.a[2] = hs_h;
        s.b[0] = WaT_h; s.b[1] = WaT_h; s.b[2] = WaT_l;
        gemm_fp16<1,3><<<dim3(HH/128, NB*TS/128, 1), 256, GEMM_SMEM>>>(
            s, nullptr, proj_h, proj_l, nullptr, 1.0f / 32.0f,
            1024, HH, 0, 0, (long long)TT * HH);
    }

    // G2 (approx): score[b] = ht_h[b] @ proj_h[b]^T  (single fp16), fp16 out
    {
        SegArgsH s{};
        s.a[0] = ht_h;
        s.b[0] = proj_h;
        gemm_fp16<3,1><<<dim3(TS/128, TT/128, NB), 256, GEMM_SMEM>>>(
            s, nullptr, score, nullptr, nullptr, 1.0f,
            1024, TS, (long long)TT * HH, (long long)TS * HH, (long long)TT * TS);
    }

    // Fused: select + exact rescore + softmax + gather -> c_h
    attend<<<NB * TT, 256>>>(score, ht, proj_h, proj_l, hs, c_h, lens);

    // G4: out = tanh([c|ht] @ W_c + b)  (single fp16, 2 segments over K=2048)
    {
        SegArgsH s{};
        s.a[0] = c_h;   s.a[1] = ht_h;
        s.b[0] = WcT_h; s.b[1] = WcT_h + 1024;
        gemm_fp16<2,2><<<dim3(OO/128, NB*TT/128, 1), 256, GEMM_SMEM>>>(
            s, out, nullptr, nullptr, bias, 1.0f,
            2048, OO, 0, 0, 0);
    }
}

// round 13
// speedup vs baseline: 1.1246x; 1.0159x over previous
#include <cuda_runtime.h>
#include <cuda_fp16.h>
#include <math.h>
#include <cstdint>

// Problem shape (fixed)
#define NB 16
#define TT 1024
#define TS 1024
#define HH 1024
#define OO 1024

// ---------------------------------------------------------------------------
// Scratch (device globals; no allocation). _h/_l = exact fp16 hi/lo pairs.
// ---------------------------------------------------------------------------
__device__ __half g_hs_h  [(size_t)NB * TS * HH];
__device__ __half g_hs_l  [(size_t)NB * TS * HH];
__device__ __half g_ht_h  [(size_t)NB * TT * HH];
__device__ __half g_WaT_h [(size_t)HH * HH];        // scaled by 32
__device__ __half g_WaT_l [(size_t)HH * HH];        // scaled by 32
__device__ __half g_proj_h[(size_t)NB * TS * HH];
__device__ __half g_proj_l[(size_t)NB * TS * HH];
__device__ __half g_c_h   [(size_t)NB * TT * HH];   // c fp16
__device__ __half g_WcT_h [(size_t)OO * 2 * HH];    // [O=1024][K=2048] fp16
__device__ __half g_score [(size_t)NB * TT * TS];   // approx scores fp16
__device__ int    g_lens  [NB];

// ---------------------------------------------------------------------------
// Helpers / PTX (base ISA only)
// ---------------------------------------------------------------------------
__device__ __forceinline__ uint32_t smem_u32(const void* p) {
    uint32_t a;
    asm("{ .reg .u64 t; cvta.to.shared.u64 t, %1; cvt.u32.u64 %0, t; }"
        : "=r"(a) : "l"(p));
    return a;
}

#define CPASYNC16(saddr, gaddr) \
    asm volatile("cp.async.cg.shared.global [%0], [%1], 16;" :: "r"(saddr), "l"(gaddr))

__device__ __forceinline__ void ldm4(uint32_t* r, uint32_t addr) {
    asm volatile("ldmatrix.sync.aligned.m8n8.x4.shared.b16 {%0,%1,%2,%3}, [%4];"
                 : "=r"(r[0]), "=r"(r[1]), "=r"(r[2]), "=r"(r[3]) : "r"(addr));
}
__device__ __forceinline__ void mma16h(float* c, const uint32_t* a, const uint32_t* b) {
    asm volatile(
        "mma.sync.aligned.m16n8k16.row.col.f32.f16.f16.f32 "
        "{%0,%1,%2,%3}, {%4,%5,%6,%7}, {%8,%9}, {%0,%1,%2,%3};"
        : "+f"(c[0]), "+f"(c[1]), "+f"(c[2]), "+f"(c[3])
        : "r"(a[0]), "r"(a[1]), "r"(a[2]), "r"(a[3]), "r"(b[0]), "r"(b[1]));
}

struct SegArgsH { const __half* a[3]; const __half* b[3]; };

static const int NSTG = 3;                       // 3 stages -> 2 CTAs/SM
static const int STAGE = 32768;                  // 16KB A + 16KB B
static const int GEMM_SMEM = 1024 + NSTG * STAGE;

// ---------------------------------------------------------------------------
// fp16 GEMM: C[M,N] = sum_seg A_seg[M,1024] * B_seg[N,1024]^T (fp16 in, fp32 acc)
// EPI: 1 fp16 split out (scaled), 2 tanh(x+bias) fp32, 3 fp16 single out
// ---------------------------------------------------------------------------
template <int EPI, int NSEG>
__global__ __launch_bounds__(256, 2)
void gemm_fp16(const SegArgsH segs, float* __restrict__ Cf,
               __half* __restrict__ Ch, __half* __restrict__ Ch2,
               const float* __restrict__ bias, float oscale,
               int ldb, int ldc, long long sA, long long sB, long long sC)
{
    extern __shared__ char smem[];
    const uint32_t data = (smem_u32(smem) + 1023) & ~1023u;

    const int tid  = threadIdx.x;
    const int lane = tid & 31;
    const int warp = tid >> 5;
    const int wm = (warp >> 2) << 6;
    const int wn = (warp & 3) << 5;
    const int bm = blockIdx.y << 7;
    const int bn = blockIdx.x << 7;

    const long long zA = (long long)blockIdx.z * sA;
    const long long zB = (long long)blockIdx.z * sB;

    const int KT = NSEG * 16;            // k-steps of 64 fp16

    auto fill = [&](int kt, int s) {
        const int seg = kt >> 4;
        const int ka  = (kt & 15) << 6;
        const __half* Ap = segs.a[seg] + zA;
        const __half* Bp = segs.b[seg] + zB;
        const uint32_t sa = data + s * STAGE;
        const uint32_t sb = sa + 16384;
#pragma unroll
        for (int i = 0; i < 4; i++) {
            int c = tid + (i << 8);
            int row = c >> 3, ch = c & 7;
            const __half* g = Ap + (size_t)(bm + row) * 1024 + ka + (ch << 3);
            CPASYNC16(sa + (row << 7) + (((ch ^ (row & 7))) << 4), g);
        }
#pragma unroll
        for (int i = 0; i < 4; i++) {
            int c = tid + (i << 8);
            int row = c >> 3, ch = c & 7;
            const __half* g = Bp + (size_t)(bn + row) * ldb + ka + (ch << 3);
            CPASYNC16(sb + (row << 7) + (((ch ^ (row & 7))) << 4), g);
        }
    };

    fill(0, 0);
    asm volatile("cp.async.commit_group;" ::: "memory");
    fill(1, 1);
    asm volatile("cp.async.commit_group;" ::: "memory");

    float acc[4][4][4];
#pragma unroll
    for (int a = 0; a < 4; a++)
#pragma unroll
        for (int b = 0; b < 4; b++)
#pragma unroll
            for (int c = 0; c < 4; c++) acc[a][b][c] = 0.f;

    const int r8   = lane & 7;
    const int tile = lane >> 3;
    const int amo  = (tile & 1) << 3;
    const int akc  = tile >> 1;
    const int bno  = (lane >> 4) << 3;
    const int bkc  = (lane >> 3) & 1;

    int sc = 0;
    for (int kt = 0; kt < KT; kt++) {
        asm volatile("cp.async.wait_group 1;" ::: "memory");
        __syncthreads();

        int nf = kt + 2;
        int fs = (sc == 0) ? 2 : sc - 1;
        if (nf < KT) fill(nf, fs);
        asm volatile("cp.async.commit_group;" ::: "memory");

        const uint32_t Ab = data + sc * STAGE;
        const uint32_t Bs = Ab + 16384;
#pragma unroll
        for (int k16 = 0; k16 < 4; k16++) {
            uint32_t af[4][4], bf[2][4];
#pragma unroll
            for (int mt = 0; mt < 4; mt++) {
                int arow = wm + mt * 16 + r8 + amo;
                int achk = 2 * k16 + akc;
                ldm4(af[mt], Ab + (arow << 7) + (((achk ^ (arow & 7))) << 4));
            }
#pragma unroll
            for (int p = 0; p < 2; p++) {
                int brow = wn + (p << 4) + r8 + bno;
                int bchk = 2 * k16 + bkc;
                ldm4(bf[p], Bs + (brow << 7) + (((bchk ^ (brow & 7))) << 4));
            }
#pragma unroll
            for (int mt = 0; mt < 4; mt++)
#pragma unroll
                for (int nt = 0; nt < 4; nt++)
                    mma16h(acc[mt][nt], af[mt], &bf[nt >> 1][(nt & 1) << 1]);
        }
        sc = (sc == 2) ? 0 : sc + 1;
    }

    const int row0 = bm + wm + (lane >> 2);
    const int col0 = bn + wn + ((lane & 3) << 1);
#pragma unroll
    for (int mt = 0; mt < 4; mt++) {
#pragma unroll
        for (int nt = 0; nt < 4; nt++) {
            int col = col0 + nt * 8;
#pragma unroll
            for (int h = 0; h < 2; h++) {
                int row = row0 + mt * 16 + h * 8;
                float v0 = acc[mt][nt][2 * h + 0];
                float v1 = acc[mt][nt][2 * h + 1];
                size_t off = (size_t)blockIdx.z * sC + (size_t)row * ldc + col;
                if (EPI == 1) {                 // scaled fp16 split
                    v0 *= oscale; v1 *= oscale;
                    __half h0 = __float2half_rn(v0);
                    __half h1 = __float2half_rn(v1);
                    __half2 hv; hv.x = h0; hv.y = h1;
                    __half2 lv;
                    lv.x = __float2half_rn(v0 - __half2float(h0));
                    lv.y = __float2half_rn(v1 - __half2float(h1));
                    *(__half2*)(Ch + off)  = hv;
                    *(__half2*)(Ch2 + off) = lv;
                } else if (EPI == 2) {          // tanh + bias -> fp32
                    float2 o = {tanhf(v0 + bias[col]), tanhf(v1 + bias[col + 1])};
                    *(float2*)(Cf + off) = o;
                } else {                        // EPI == 3: fp16 single
                    __half2 hv;
                    hv.x = __float2half_rn(v0);
                    hv.y = __float2half_rn(v1);
                    *(__half2*)(Ch + off) = hv;
                }
            }
        }
    }
}

// ---------------------------------------------------------------------------
// Preprocessing
// ---------------------------------------------------------------------------
__global__ void prep_split(const float* __restrict__ in, __half* __restrict__ hh,
                           __half* __restrict__ hl, size_t n4)
{
    size_t i  = (size_t)blockIdx.x * blockDim.x + threadIdx.x;
    size_t st = (size_t)gridDim.x * blockDim.x;
    for (; i < n4; i += st) {
        float4 v = ((const float4*)in)[i];
        __half2 h0, h1, l0, l1;
        h0.x = __float2half_rn(v.x); l0.x = __float2half_rn(v.x - __half2float(h0.x));
        h0.y = __float2half_rn(v.y); l0.y = __float2half_rn(v.y - __half2float(h0.y));
        h1.x = __float2half_rn(v.z); l1.x = __float2half_rn(v.z - __half2float(h1.x));
        h1.y = __float2half_rn(v.w); l1.y = __float2half_rn(v.w - __half2float(h1.y));
        ((__half2*)hh)[2 * i]     = h0;
        ((__half2*)hh)[2 * i + 1] = h1;
        ((__half2*)hl)[2 * i]     = l0;
        ((__half2*)hl)[2 * i + 1] = l1;
    }
}

__global__ void prep_half(const float* __restrict__ in, __half* __restrict__ out,
                          size_t n4)
{
    size_t i  = (size_t)blockIdx.x * blockDim.x + threadIdx.x;
    size_t st = (size_t)gridDim.x * blockDim.x;
    for (; i < n4; i += st) {
        float4 v = ((const float4*)in)[i];
        __half2 h0, h1;
        h0.x = __float2half_rn(v.x); h0.y = __float2half_rn(v.y);
        h1.x = __float2half_rn(v.z); h1.y = __float2half_rn(v.w);
        ((__half2*)out)[2 * i]     = h0;
        ((__half2*)out)[2 * i + 1] = h1;
    }
}

// Merged weight prep: blockIdx.y < 32 -> Wa (fp16 split, scaled 32, transpose);
// else -> Wc (fp16 single, transpose).
__global__ void prep_w(const float* __restrict__ Wa, const float* __restrict__ Wc,
                       __half* __restrict__ WaT_h, __half* __restrict__ WaT_l,
                       __half* __restrict__ WcT_h)
{
    __shared__ float t[32][33];
    int y = blockIdx.y;
    bool isWa = (y < 32);
    const float* src = isWa ? Wa : Wc;
    int r0 = (isWa ? y : (y - 32)) << 5;
    int c0 = blockIdx.x << 5;
    int tx = threadIdx.x, ty = threadIdx.y;
#pragma unroll
    for (int i = 0; i < 32; i += 8)
        t[ty + i][tx] = src[(size_t)(r0 + ty + i) * 1024 + c0 + tx];
    __syncthreads();
    if (isWa) {
#pragma unroll
        for (int i = 0; i < 32; i += 8) {
            float v = 32.0f * t[tx][ty + i];
            __half h = __float2half_rn(v);
            __half l = __float2half_rn(v - __half2float(h));
            size_t idx = (size_t)(c0 + ty + i) * 1024 + r0 + tx;
            WaT_h[idx] = h;
            WaT_l[idx] = l;
        }
    } else {
#pragma unroll
        for (int i = 0; i < 32; i += 8) {
            size_t idx = (size_t)(c0 + ty + i) * 2048 + r0 + tx;
            WcT_h[idx] = __float2half_rn(t[tx][ty + i]);
        }
    }
}

__global__ void lens_kernel(const int* __restrict__ source, int* __restrict__ lens)
{
    int b = blockIdx.x, tid = threadIdx.x;
    int cnt = 0;
    for (int s = tid; s < TS; s += blockDim.x)
        cnt += (source[(size_t)b * TS + s] != 0);
    __shared__ int red[256];
    red[tid] = cnt;
    __syncthreads();
    for (int s = 128; s > 0; s >>= 1) {
        if (tid < s) red[tid] += red[tid + s];
        __syncthreads();
    }
    if (tid == 0) lens[b] = red[0];
}

// ---------------------------------------------------------------------------
// Fused attend (block-per-row): select candidates from fp16 approx scores
// (cutoff max-10), exact-rescore via half2 loads (fp32 ht . (proj_h+proj_l)),
// warp-parallel softmax, dense gather -> c fp16.
// ---------------------------------------------------------------------------
#define CAP 64
__global__ __launch_bounds__(256)
void attend(const __half* __restrict__ score, const float* __restrict__ ht,
            const __half* __restrict__ proj_h, const __half* __restrict__ proj_l,
            const float* __restrict__ hs, __half* __restrict__ c_h,
            const int* __restrict__ lens)
{
    __shared__ float htrow[1024];
    __shared__ int   cand[CAP];
    __shared__ float exsc[CAP];
    __shared__ float wred[8];
    __shared__ int   ccnt;
    __shared__ float s_inv;

    const int row  = blockIdx.x;                 // 0 .. NB*TT-1
    const int b    = row >> 10;
    const int tid  = threadIdx.x;
    const int warp = tid >> 5, lane = tid & 31;
    const int len  = lens[b];
    const __half* srow = score + (size_t)row * TS;

    if (tid == 0) ccnt = 0;

    // ht row (fp32) into smem
    ((float4*)htrow)[tid] = ((const float4*)(ht + (size_t)row * HH))[tid];

    // load 4 fp16 scores per thread; masked max via shfl + cross-warp smem
    __half2 p0 = ((const __half2*)srow)[2 * tid];
    __half2 p1 = ((const __half2*)srow)[2 * tid + 1];
    float v0 = __half2float(p0.x), v1 = __half2float(p0.y);
    float v2 = __half2float(p1.x), v3 = __half2float(p1.y);
    int base = tid << 2;
    float m = -1e30f;
    if (base + 0 < len) m = fmaxf(m, v0);
    if (base + 1 < len) m = fmaxf(m, v1);
    if (base + 2 < len) m = fmaxf(m, v2);
    if (base + 3 < len) m = fmaxf(m, v3);
#pragma unroll
    for (int s = 16; s > 0; s >>= 1)
        m = fmaxf(m, __shfl_xor_sync(0xffffffffu, m, s));
    if (lane == 0) wred[warp] = m;
    __syncthreads();
    if (warp == 0) {
        float mm = (lane < 8) ? wred[lane] : -1e30f;
#pragma unroll
        for (int s = 4; s > 0; s >>= 1)
            mm = fmaxf(mm, __shfl_xor_sync(0xffffffffu, mm, s));
        if (lane == 0) wred[0] = mm;
    }
    __syncthreads();
    const float thr = wred[0] - 10.0f;           // 9.2 cutoff + margin

    // select candidates (few -> atomics cheap)
    if (base + 0 < len && v0 >= thr) { int p = atomicAdd(&ccnt, 1); if (p < CAP) cand[p] = base + 0; }
    if (base + 1 < len && v1 >= thr) { int p = atomicAdd(&ccnt, 1); if (p < CAP) cand[p] = base + 1; }
    if (base + 2 < len && v2 >= thr) { int p = atomicAdd(&ccnt, 1); if (p < CAP) cand[p] = base + 2; }
    if (base + 3 < len && v3 >= thr) { int p = atomicAdd(&ccnt, 1); if (p < CAP) cand[p] = base + 3; }
    __syncthreads();
    const int C = (ccnt < CAP) ? ccnt : CAP;

    // exact rescore: warp per candidate, half2 loads (16 iters of 2 elems)
    for (int ci = warp; ci < C; ci += 8) {
        int s = cand[ci];
        const __half2* ph2 = (const __half2*)(proj_h + ((size_t)b * TS + s) * HH);
        const __half2* pl2 = (const __half2*)(proj_l + ((size_t)b * TS + s) * HH);
        float acc = 0.f;
#pragma unroll
        for (int j = 0; j < 16; j++) {
            int k2 = (j << 5) + lane;            // half2 index
            __half2 h2 = ph2[k2];
            __half2 l2 = pl2[k2];
            acc = fmaf(htrow[2 * k2],     __half2float(h2.x) + __half2float(l2.x), acc);
            acc = fmaf(htrow[2 * k2 + 1], __half2float(h2.y) + __half2float(l2.y), acc);
        }
#pragma unroll
        for (int s2 = 16; s2 > 0; s2 >>= 1)
            acc += __shfl_xor_sync(0xffffffffu, acc, s2);
        if (lane == 0) exsc[ci] = acc;
    }
    __syncthreads();

    // softmax over candidates: warp 0 lane-parallel
    if (warp == 0) {
        float mx = -1e30f;
        for (int i = lane; i < C; i += 32) mx = fmaxf(mx, exsc[i]);
#pragma unroll
        for (int s = 16; s > 0; s >>= 1)
            mx = fmaxf(mx, __shfl_xor_sync(0xffffffffu, mx, s));
        float sum = 0.f;
        for (int i = lane; i < C; i += 32) {
            float e = expf(exsc[i] - mx);
            exsc[i] = e;
            sum += e;
        }
#pragma unroll
        for (int s = 16; s > 0; s >>= 1)
            sum += __shfl_xor_sync(0xffffffffu, sum, s);
        if (lane == 0) s_inv = 1.0f / sum;
    }
    __syncthreads();
    const float inv = s_inv;

    // gather: c = sum a_k * hs[s_k]  (float4 accumulator per thread)
    float4 acc4 = {0.f, 0.f, 0.f, 0.f};
    for (int ci = 0; ci < C; ci++) {
        float wgt = exsc[ci] * inv;
        float4 h = ((const float4*)(hs + ((size_t)b * TS + cand[ci]) * HH))[tid];
        acc4.x = fmaf(wgt, h.x, acc4.x);
        acc4.y = fmaf(wgt, h.y, acc4.y);
        acc4.z = fmaf(wgt, h.z, acc4.z);
        acc4.w = fmaf(wgt, h.w, acc4.w);
    }
    __half2 o0, o1;
    o0.x = __float2half_rn(acc4.x); o0.y = __float2half_rn(acc4.y);
    o1.x = __float2half_rn(acc4.z); o1.y = __float2half_rn(acc4.w);
    ((__half2*)(c_h + (size_t)row * HH))[2 * tid]     = o0;
    ((__half2*)(c_h + (size_t)row * HH))[2 * tid + 1] = o1;
}

// ---------------------------------------------------------------------------
// Host launch
// ---------------------------------------------------------------------------
extern "C" void kernel_launch(void* const* d_in, const int* in_sizes, int n_in,
                              void* d_out, int out_size)
{
    const float* ht     = (const float*)d_in[0];
    const float* hs     = (const float*)d_in[1];
    const float* W_a    = (const float*)d_in[2];
    const float* W_c    = (const float*)d_in[3];
    const float* bias   = (const float*)d_in[4];
    const int*   source = (const int*)d_in[5];
    float* out = (float*)d_out;

    __half *hs_h, *hs_l, *ht_h, *WaT_h, *WaT_l, *proj_h, *proj_l, *c_h, *WcT_h, *score;
    int* lens;
    cudaGetSymbolAddress((void**)&hs_h,   g_hs_h);
    cudaGetSymbolAddress((void**)&hs_l,   g_hs_l);
    cudaGetSymbolAddress((void**)&ht_h,   g_ht_h);
    cudaGetSymbolAddress((void**)&WaT_h,  g_WaT_h);
    cudaGetSymbolAddress((void**)&WaT_l,  g_WaT_l);
    cudaGetSymbolAddress((void**)&proj_h, g_proj_h);
    cudaGetSymbolAddress((void**)&proj_l, g_proj_l);
    cudaGetSymbolAddress((void**)&c_h,    g_c_h);
    cudaGetSymbolAddress((void**)&WcT_h,  g_WcT_h);
    cudaGetSymbolAddress((void**)&score,  g_score);
    cudaGetSymbolAddress((void**)&lens,   g_lens);

    cudaFuncSetAttribute(gemm_fp16<1,3>, cudaFuncAttributeMaxDynamicSharedMemorySize, GEMM_SMEM);
    cudaFuncSetAttribute(gemm_fp16<3,1>, cudaFuncAttributeMaxDynamicSharedMemorySize, GEMM_SMEM);
    cudaFuncSetAttribute(gemm_fp16<2,2>, cudaFuncAttributeMaxDynamicSharedMemorySize, GEMM_SMEM);

    // Preprocess (ordered so G1 is launch #4 -> ncu captures it)
    prep_w<<<dim3(32, 96), dim3(32, 8)>>>(W_a, W_c, WaT_h, WaT_l, WcT_h);      // 1
    prep_split<<<2048, 256>>>(hs, hs_h, hs_l, (size_t)NB * TS * HH / 4);       // 2
    lens_kernel<<<NB, 256>>>(source, lens);                                    // 3

    // G1: proj = hs @ W_a  (3xFP16, Wa scaled by 32) -> proj_h, proj_l (x 1/32)
    {
        SegArgsH s{};
        s.a[0] = hs_h;  s.a[1] = hs_l;  s.a[2] = hs_h;
        s.b[0] = WaT_h; s.b[1] = WaT_h; s.b[2] = WaT_l;
        gemm_fp16<1,3><<<dim3(HH/128, NB*TS/128, 1), 256, GEMM_SMEM>>>(        // 4
            s, nullptr, proj_h, proj_l, nullptr, 1.0f / 32.0f,
            1024, HH, 0, 0, (long long)TT * HH);
    }

    prep_half<<<2048, 256>>>(ht, ht_h, (size_t)NB * TT * HH / 4);              // 5

    // G2 (approx): score[b] = ht_h[b] @ proj_h[b]^T  (single fp16), fp16 out
    {
        SegArgsH s{};
        s.a[0] = ht_h;
        s.b[0] = proj_h;
        gemm_fp16<3,1><<<dim3(TS/128, TT/128, NB), 256, GEMM_SMEM>>>(          // 6
            s, nullptr, score, nullptr, nullptr, 1.0f,
            1024, TS, (long long)TT * HH, (long long)TS * HH, (long long)TT * TS);
    }

    // Fused: select + exact rescore + softmax + gather -> c_h
    attend<<<NB * TT, 256>>>(score, ht, proj_h, proj_l, hs, c_h, lens);        // 7

    // G4: out = tanh([c|ht] @ W_c + b)  (single fp16, 2 segments over K=2048)
    {
        SegArgsH s{};
        s.a[0] = c_h;   s.a[1] = ht_h;
        s.b[0] = WcT_h; s.b[1] = WcT_h + 1024;
        gemm_fp16<2,2><<<dim3(OO/128, NB*TT/128, 1), 256, GEMM_SMEM>>>(        // 8
            s, out, nullptr, nullptr, bias, 1.0f,
            2048, OO, 0, 0, 0);
    }
}

// round 15
// speedup vs baseline: 1.2510x; 1.1124x over previous
#include <cuda_runtime.h>
#include <cuda_fp16.h>
#include <math.h>
#include <cstdint>

// Problem shape (fixed)
#define NB 16
#define TT 1024
#define TS 1024
#define HH 1024
#define OO 1024

// ---------------------------------------------------------------------------
// Scratch (device globals; no allocation). _h/_l = exact fp16 hi/lo pairs.
// ---------------------------------------------------------------------------
__device__ __half g_ht_h  [(size_t)NB * TT * HH];
__device__ __half g_ht_l  [(size_t)NB * TT * HH];
__device__ __half g_hs_h  [(size_t)NB * TS * HH];
__device__ __half g_Wa_h  [(size_t)HH * HH];        // Wa row-major, scaled by 32
__device__ __half g_Wa_l  [(size_t)HH * HH];        // Wa lo, scaled by 32
__device__ __half g_q_h   [(size_t)NB * TT * HH];   // q = ht @ Wa^T, hi
__device__ __half g_q_l   [(size_t)NB * TT * HH];   // q lo
__device__ __half g_c_h   [(size_t)NB * TT * HH];   // c fp16
__device__ __half g_WcT_h [(size_t)OO * 2 * HH];    // [O=1024][K=2048] fp16
__device__ __half g_score [(size_t)NB * TT * TS];   // approx scores fp16
__device__ int    g_lens  [NB];

// ---------------------------------------------------------------------------
// Helpers / PTX (base ISA only)
// ---------------------------------------------------------------------------
__device__ __forceinline__ uint32_t smem_u32(const void* p) {
    uint32_t a;
    asm("{ .reg .u64 t; cvta.to.shared.u64 t, %1; cvt.u32.u64 %0, t; }"
        : "=r"(a) : "l"(p));
    return a;
}

#define CPASYNC16(saddr, gaddr) \
    asm volatile("cp.async.cg.shared.global [%0], [%1], 16;" :: "r"(saddr), "l"(gaddr))

__device__ __forceinline__ void ldm4(uint32_t* r, uint32_t addr) {
    asm volatile("ldmatrix.sync.aligned.m8n8.x4.shared.b16 {%0,%1,%2,%3}, [%4];"
                 : "=r"(r[0]), "=r"(r[1]), "=r"(r[2]), "=r"(r[3]) : "r"(addr));
}
__device__ __forceinline__ void mma16h(float* c, const uint32_t* a, const uint32_t* b) {
    asm volatile(
        "mma.sync.aligned.m16n8k16.row.col.f32.f16.f16.f32 "
        "{%0,%1,%2,%3}, {%4,%5,%6,%7}, {%8,%9}, {%0,%1,%2,%3};"
        : "+f"(c[0]), "+f"(c[1]), "+f"(c[2]), "+f"(c[3])
        : "r"(a[0]), "r"(a[1]), "r"(a[2]), "r"(a[3]), "r"(b[0]), "r"(b[1]));
}

struct SegArgsH { const __half* a[3]; const __half* b[3]; };

static const int NSTG = 3;                       // 3 stages -> 2 CTAs/SM
static const int STAGE = 32768;                  // 16KB A + 16KB B
static const int GEMM_SMEM = 1024 + NSTG * STAGE;

// ---------------------------------------------------------------------------
// fp16 GEMM: C[M,N] = sum_seg A_seg[M,1024] * B_seg[N,1024]^T (fp16 in, fp32 acc)
// EPI: 1 fp16 split out (scaled), 2 tanh(x+bias) fp32, 3 fp16 single out
// ---------------------------------------------------------------------------
template <int EPI, int NSEG>
__global__ __launch_bounds__(256, 2)
void gemm_fp16(const SegArgsH segs, float* __restrict__ Cf,
               __half* __restrict__ Ch, __half* __restrict__ Ch2,
               const float* __restrict__ bias, float oscale,
               int ldb, int ldc, long long sA, long long sB, long long sC)
{
    extern __shared__ char smem[];
    const uint32_t data = (smem_u32(smem) + 1023) & ~1023u;

    const int tid  = threadIdx.x;
    const int lane = tid & 31;
    const int warp = tid >> 5;
    const int wm = (warp >> 2) << 6;
    const int wn = (warp & 3) << 5;
    const int bm = blockIdx.y << 7;
    const int bn = blockIdx.x << 7;

    const long long zA = (long long)blockIdx.z * sA;
    const long long zB = (long long)blockIdx.z * sB;

    const int KT = NSEG * 16;            // k-steps of 64 fp16

    auto fill = [&](int kt, int s) {
        const int seg = kt >> 4;
        const int ka  = (kt & 15) << 6;
        const __half* Ap = segs.a[seg] + zA;
        const __half* Bp = segs.b[seg] + zB;
        const uint32_t sa = data + s * STAGE;
        const uint32_t sb = sa + 16384;
#pragma unroll
        for (int i = 0; i < 4; i++) {
            int c = tid + (i << 8);
            int row = c >> 3, ch = c & 7;
            const __half* g = Ap + (size_t)(bm + row) * 1024 + ka + (ch << 3);
            CPASYNC16(sa + (row << 7) + (((ch ^ (row & 7))) << 4), g);
        }
#pragma unroll
        for (int i = 0; i < 4; i++) {
            int c = tid + (i << 8);
            int row = c >> 3, ch = c & 7;
            const __half* g = Bp + (size_t)(bn + row) * ldb + ka + (ch << 3);
            CPASYNC16(sb + (row << 7) + (((ch ^ (row & 7))) << 4), g);
        }
    };

    fill(0, 0);
    asm volatile("cp.async.commit_group;" ::: "memory");
    fill(1, 1);
    asm volatile("cp.async.commit_group;" ::: "memory");

    float acc[4][4][4];
#pragma unroll
    for (int a = 0; a < 4; a++)
#pragma unroll
        for (int b = 0; b < 4; b++)
#pragma unroll
            for (int c = 0; c < 4; c++) acc[a][b][c] = 0.f;

    const int r8   = lane & 7;
    const int tile = lane >> 3;
    const int amo  = (tile & 1) << 3;
    const int akc  = tile >> 1;
    const int bno  = (lane >> 4) << 3;
    const int bkc  = (lane >> 3) & 1;

    int sc = 0;
    for (int kt = 0; kt < KT; kt++) {
        asm volatile("cp.async.wait_group 1;" ::: "memory");
        __syncthreads();

        int nf = kt + 2;
        int fs = (sc == 0) ? 2 : sc - 1;
        if (nf < KT) fill(nf, fs);
        asm volatile("cp.async.commit_group;" ::: "memory");

        const uint32_t Ab = data + sc * STAGE;
        const uint32_t Bs = Ab + 16384;
#pragma unroll
        for (int k16 = 0; k16 < 4; k16++) {
            uint32_t af[4][4], bf[2][4];
#pragma unroll
            for (int mt = 0; mt < 4; mt++) {
                int arow = wm + mt * 16 + r8 + amo;
                int achk = 2 * k16 + akc;
                ldm4(af[mt], Ab + (arow << 7) + (((achk ^ (arow & 7))) << 4));
            }
#pragma unroll
            for (int p = 0; p < 2; p++) {
                int brow = wn + (p << 4) + r8 + bno;
                int bchk = 2 * k16 + bkc;
                ldm4(bf[p], Bs + (brow << 7) + (((bchk ^ (brow & 7))) << 4));
            }
#pragma unroll
            for (int mt = 0; mt < 4; mt++)
#pragma unroll
                for (int nt = 0; nt < 4; nt++)
                    mma16h(acc[mt][nt], af[mt], &bf[nt >> 1][(nt & 1) << 1]);
        }
        sc = (sc == 2) ? 0 : sc + 1;
    }

    const int row0 = bm + wm + (lane >> 2);
    const int col0 = bn + wn + ((lane & 3) << 1);
#pragma unroll
    for (int mt = 0; mt < 4; mt++) {
#pragma unroll
        for (int nt = 0; nt < 4; nt++) {
            int col = col0 + nt * 8;
#pragma unroll
            for (int h = 0; h < 2; h++) {
                int row = row0 + mt * 16 + h * 8;
                float v0 = acc[mt][nt][2 * h + 0];
                float v1 = acc[mt][nt][2 * h + 1];
                size_t off = (size_t)blockIdx.z * sC + (size_t)row * ldc + col;
                if (EPI == 1) {                 // scaled fp16 split
                    v0 *= oscale; v1 *= oscale;
                    __half h0 = __float2half_rn(v0);
                    __half h1 = __float2half_rn(v1);
                    __half2 hv; hv.x = h0; hv.y = h1;
                    __half2 lv;
                    lv.x = __float2half_rn(v0 - __half2float(h0));
                    lv.y = __float2half_rn(v1 - __half2float(h1));
                    *(__half2*)(Ch + off)  = hv;
                    *(__half2*)(Ch2 + off) = lv;
                } else if (EPI == 2) {          // tanh + bias -> fp32
                    float2 o = {tanhf(v0 + bias[col]), tanhf(v1 + bias[col + 1])};
                    *(float2*)(Cf + off) = o;
                } else {                        // EPI == 3: fp16 single
                    __half2 hv;
                    hv.x = __float2half_rn(v0);
                    hv.y = __float2half_rn(v1);
                    *(__half2*)(Ch + off) = hv;
                }
            }
        }
    }
}

// ---------------------------------------------------------------------------
// Preprocessing
// ---------------------------------------------------------------------------
__global__ void prep_split(const float* __restrict__ in, __half* __restrict__ hh,
                           __half* __restrict__ hl, size_t n4)
{
    size_t i  = (size_t)blockIdx.x * blockDim.x + threadIdx.x;
    size_t st = (size_t)gridDim.x * blockDim.x;
    for (; i < n4; i += st) {
        float4 v = ((const float4*)in)[i];
        __half2 h0, h1, l0, l1;
        h0.x = __float2half_rn(v.x); l0.x = __float2half_rn(v.x - __half2float(h0.x));
        h0.y = __float2half_rn(v.y); l0.y = __float2half_rn(v.y - __half2float(h0.y));
        h1.x = __float2half_rn(v.z); l1.x = __float2half_rn(v.z - __half2float(h1.x));
        h1.y = __float2half_rn(v.w); l1.y = __float2half_rn(v.w - __half2float(h1.y));
        ((__half2*)hh)[2 * i]     = h0;
        ((__half2*)hh)[2 * i + 1] = h1;
        ((__half2*)hl)[2 * i]     = l0;
        ((__half2*)hl)[2 * i + 1] = l1;
    }
}

// Wa (no transpose!): scaled-by-32 fp16 split, row-major pass-through
__global__ void prep_wa(const float* __restrict__ Wa, __half* __restrict__ hh,
                        __half* __restrict__ hl, size_t n4)
{
    size_t i  = (size_t)blockIdx.x * blockDim.x + threadIdx.x;
    size_t st = (size_t)gridDim.x * blockDim.x;
    for (; i < n4; i += st) {
        float4 v = ((const float4*)Wa)[i];
        v.x *= 32.0f; v.y *= 32.0f; v.z *= 32.0f; v.w *= 32.0f;
        __half2 h0, h1, l0, l1;
        h0.x = __float2half_rn(v.x); l0.x = __float2half_rn(v.x - __half2float(h0.x));
        h0.y = __float2half_rn(v.y); l0.y = __float2half_rn(v.y - __half2float(h0.y));
        h1.x = __float2half_rn(v.z); l1.x = __float2half_rn(v.z - __half2float(h1.x));
        h1.y = __float2half_rn(v.w); l1.y = __float2half_rn(v.w - __half2float(h1.y));
        ((__half2*)hh)[2 * i]     = h0;
        ((__half2*)hh)[2 * i + 1] = h1;
        ((__half2*)hl)[2 * i]     = l0;
        ((__half2*)hl)[2 * i + 1] = l1;
    }
}

__global__ void prep_half(const float* __restrict__ in, __half* __restrict__ out,
                          size_t n4)
{
    size_t i  = (size_t)blockIdx.x * blockDim.x + threadIdx.x;
    size_t st = (size_t)gridDim.x * blockDim.x;
    for (; i < n4; i += st) {
        float4 v = ((const float4*)in)[i];
        __half2 h0, h1;
        h0.x = __float2half_rn(v.x); h0.y = __float2half_rn(v.y);
        h1.x = __float2half_rn(v.z); h1.y = __float2half_rn(v.w);
        ((__half2*)out)[2 * i]     = h0;
        ((__half2*)out)[2 * i + 1] = h1;
    }
}

// Wc: dst[c][r] = fp16(src[r][c])  (transpose, [O][2048])
__global__ void prep_wc(const float* __restrict__ Wc, __half* __restrict__ WcT_h)
{
    __shared__ float t[32][33];
    int r0 = blockIdx.y << 5;      // K index (0..2047)
    int c0 = blockIdx.x << 5;      // O index
    int tx = threadIdx.x, ty = threadIdx.y;
#pragma unroll
    for (int i = 0; i < 32; i += 8)
        t[ty + i][tx] = Wc[(size_t)(r0 + ty + i) * 1024 + c0 + tx];
    __syncthreads();
#pragma unroll
    for (int i = 0; i < 32; i += 8) {
        size_t idx = (size_t)(c0 + ty + i) * 2048 + r0 + tx;
        WcT_h[idx] = __float2half_rn(t[tx][ty + i]);
    }
}

__global__ void lens_kernel(const int* __restrict__ source, int* __restrict__ lens)
{
    int b = blockIdx.x, tid = threadIdx.x;
    int cnt = 0;
    for (int s = tid; s < TS; s += blockDim.x)
        cnt += (source[(size_t)b * TS + s] != 0);
    __shared__ int red[256];
    red[tid] = cnt;
    __syncthreads();
    for (int s = 128; s > 0; s >>= 1) {
        if (tid < s) red[tid] += red[tid + s];
        __syncthreads();
    }
    if (tid == 0) lens[b] = red[0];
}

// ---------------------------------------------------------------------------
// Fused attend (block-per-row): select candidates from fp16 approx scores
// (cutoff max-10), exact-rescore (fp32 (q_h+q_l) . hs_s with hs fp32 — the
// same rows the gather loads, so the second read hits L1), softmax, gather.
// ---------------------------------------------------------------------------
#define CAP 64
__global__ __launch_bounds__(256)
void attend(const __half* __restrict__ score,
            const __half* __restrict__ q_h, const __half* __restrict__ q_l,
            const float* __restrict__ hs, __half* __restrict__ c_h,
            const int* __restrict__ lens)
{
    __shared__ float qrow[1024];
    __shared__ int   cand[CAP];
    __shared__ float exsc[CAP];
    __shared__ float wred[8];
    __shared__ int   ccnt;
    __shared__ float s_inv;

    const int row  = blockIdx.x;                 // 0 .. NB*TT-1
    const int b    = row >> 10;
    const int tid  = threadIdx.x;
    const int warp = tid >> 5, lane = tid & 31;
    const int len  = lens[b];
    const __half* srow = score + (size_t)row * TS;

    if (tid == 0) ccnt = 0;

    // q row (fp32 = h + l) into smem
    {
        __half2 qh0 = ((const __half2*)(q_h + (size_t)row * HH))[2 * tid];
        __half2 qh1 = ((const __half2*)(q_h + (size_t)row * HH))[2 * tid + 1];
        __half2 ql0 = ((const __half2*)(q_l + (size_t)row * HH))[2 * tid];
        __half2 ql1 = ((const __half2*)(q_l + (size_t)row * HH))[2 * tid + 1];
        float4 qv;
        qv.x = __half2float(qh0.x) + __half2float(ql0.x);
        qv.y = __half2float(qh0.y) + __half2float(ql0.y);
        qv.z = __half2float(qh1.x) + __half2float(ql1.x);
        qv.w = __half2float(qh1.y) + __half2float(ql1.y);
        ((float4*)qrow)[tid] = qv;
    }

    // load 4 fp16 scores per thread; masked max via shfl + cross-warp smem
    __half2 p0 = ((const __half2*)srow)[2 * tid];
    __half2 p1 = ((const __half2*)srow)[2 * tid + 1];
    float v0 = __half2float(p0.x), v1 = __half2float(p0.y);
    float v2 = __half2float(p1.x), v3 = __half2float(p1.y);
    int base = tid << 2;
    float m = -1e30f;
    if (base + 0 < len) m = fmaxf(m, v0);
    if (base + 1 < len) m = fmaxf(m, v1);
    if (base + 2 < len) m = fmaxf(m, v2);
    if (base + 3 < len) m = fmaxf(m, v3);
#pragma unroll
    for (int s = 16; s > 0; s >>= 1)
        m = fmaxf(m, __shfl_xor_sync(0xffffffffu, m, s));
    if (lane == 0) wred[warp] = m;
    __syncthreads();
    if (warp == 0) {
        float mm = (lane < 8) ? wred[lane] : -1e30f;
#pragma unroll
        for (int s = 4; s > 0; s >>= 1)
            mm = fmaxf(mm, __shfl_xor_sync(0xffffffffu, mm, s));
        if (lane == 0) wred[0] = mm;
    }
    __syncthreads();
    const float thr = wred[0] - 10.0f;           // 9.2 cutoff + margin

    // select candidates (few -> atomics cheap)
    if (base + 0 < len && v0 >= thr) { int p = atomicAdd(&ccnt, 1); if (p < CAP) cand[p] = base + 0; }
    if (base + 1 < len && v1 >= thr) { int p = atomicAdd(&ccnt, 1); if (p < CAP) cand[p] = base + 1; }
    if (base + 2 < len && v2 >= thr) { int p = atomicAdd(&ccnt, 1); if (p < CAP) cand[p] = base + 2; }
    if (base + 3 < len && v3 >= thr) { int p = atomicAdd(&ccnt, 1); if (p < CAP) cand[p] = base + 3; }
    __syncthreads();
    const int C = (ccnt < CAP) ? ccnt : CAP;

    // exact rescore: warp per candidate, fp32 hs rows (float4 loads)
    for (int ci = warp; ci < C; ci += 8) {
        const float4* hr = (const float4*)(hs + ((size_t)b * TS + cand[ci]) * HH);
        float acc = 0.f;
#pragma unroll
        for (int j = 0; j < 8; j++) {
            int k4 = (j << 5) + lane;            // float4 index
            float4 h4 = hr[k4];
            const float* q4 = &qrow[k4 << 2];
            acc = fmaf(q4[0], h4.x, acc);
            acc = fmaf(q4[1], h4.y, acc);
            acc = fmaf(q4[2], h4.z, acc);
            acc = fmaf(q4[3], h4.w, acc);
        }
#pragma unroll
        for (int s2 = 16; s2 > 0; s2 >>= 1)
            acc += __shfl_xor_sync(0xffffffffu, acc, s2);
        if (lane == 0) exsc[ci] = acc;
    }
    __syncthreads();

    // softmax over candidates: warp 0 lane-parallel
    if (warp == 0) {
        float mx = -1e30f;
        for (int i = lane; i < C; i += 32) mx = fmaxf(mx, exsc[i]);
#pragma unroll
        for (int s = 16; s > 0; s >>= 1)
            mx = fmaxf(mx, __shfl_xor_sync(0xffffffffu, mx, s));
        float sum = 0.f;
        for (int i = lane; i < C; i += 32) {
            float e = expf(exsc[i] - mx);
            exsc[i] = e;
            sum += e;
        }
#pragma unroll
        for (int s = 16; s > 0; s >>= 1)
            sum += __shfl_xor_sync(0xffffffffu, sum, s);
        if (lane == 0) s_inv = 1.0f / sum;
    }
    __syncthreads();
    const float inv = s_inv;

    // gather: c = sum a_k * hs[s_k]  (float4 accumulator; rows are L1-warm)
    float4 acc4 = {0.f, 0.f, 0.f, 0.f};
    for (int ci = 0; ci < C; ci++) {
        float wgt = exsc[ci] * inv;
        float4 h = ((const float4*)(hs + ((size_t)b * TS + cand[ci]) * HH))[tid];
        acc4.x = fmaf(wgt, h.x, acc4.x);
        acc4.y = fmaf(wgt, h.y, acc4.y);
        acc4.z = fmaf(wgt, h.z, acc4.z);
        acc4.w = fmaf(wgt, h.w, acc4.w);
    }
    __half2 o0, o1;
    o0.x = __float2half_rn(acc4.x); o0.y = __float2half_rn(acc4.y);
    o1.x = __float2half_rn(acc4.z); o1.y = __float2half_rn(acc4.w);
    ((__half2*)(c_h + (size_t)row * HH))[2 * tid]     = o0;
    ((__half2*)(c_h + (size_t)row * HH))[2 * tid + 1] = o1;
}

// ---------------------------------------------------------------------------
// Host launch
// ---------------------------------------------------------------------------
extern "C" void kernel_launch(void* const* d_in, const int* in_sizes, int n_in,
                              void* d_out, int out_size)
{
    const float* ht     = (const float*)d_in[0];
    const float* hs     = (const float*)d_in[1];
    const float* W_a    = (const float*)d_in[2];
    const float* W_c    = (const float*)d_in[3];
    const float* bias   = (const float*)d_in[4];
    const int*   source = (const int*)d_in[5];
    float* out = (float*)d_out;

    __half *ht_h, *ht_l, *hs_h, *Wa_h, *Wa_l, *q_h, *q_l, *c_h, *WcT_h, *score;
    int* lens;
    cudaGetSymbolAddress((void**)&ht_h,   g_ht_h);
    cudaGetSymbolAddress((void**)&ht_l,   g_ht_l);
    cudaGetSymbolAddress((void**)&hs_h,   g_hs_h);
    cudaGetSymbolAddress((void**)&Wa_h,   g_Wa_h);
    cudaGetSymbolAddress((void**)&Wa_l,   g_Wa_l);
    cudaGetSymbolAddress((void**)&q_h,    g_q_h);
    cudaGetSymbolAddress((void**)&q_l,    g_q_l);
    cudaGetSymbolAddress((void**)&c_h,    g_c_h);
    cudaGetSymbolAddress((void**)&WcT_h,  g_WcT_h);
    cudaGetSymbolAddress((void**)&score,  g_score);
    cudaGetSymbolAddress((void**)&lens,   g_lens);

    cudaFuncSetAttribute(gemm_fp16<1,3>, cudaFuncAttributeMaxDynamicSharedMemorySize, GEMM_SMEM);
    cudaFuncSetAttribute(gemm_fp16<3,1>, cudaFuncAttributeMaxDynamicSharedMemorySize, GEMM_SMEM);
    cudaFuncSetAttribute(gemm_fp16<2,2>, cudaFuncAttributeMaxDynamicSharedMemorySize, GEMM_SMEM);

    // Preprocess (G1 stays launch #4 for ncu)
    prep_wa<<<256, 256>>>(W_a, Wa_h, Wa_l, (size_t)HH * HH / 4);               // 1
    prep_split<<<2048, 256>>>(ht, ht_h, ht_l, (size_t)NB * TT * HH / 4);       // 2
    lens_kernel<<<NB, 256>>>(source, lens);                                    // 3

    // G1: q = ht @ Wa^T  (3xFP16, Wa scaled by 32) -> q_h, q_l (x 1/32)
    //     B operand = Wa row-major [m][h]  (C = A . B^T gives q[t,m])
    {
        SegArgsH s{};
        s.a[0] = ht_h; s.a[1] = ht_l; s.a[2] = ht_h;
        s.b[0] = Wa_h; s.b[1] = Wa_h; s.b[2] = Wa_l;
        gemm_fp16<1,3><<<dim3(HH/128, NB*TT/128, 1), 256, GEMM_SMEM>>>(        // 4
            s, nullptr, q_h, q_l, nullptr, 1.0f / 32.0f,
            1024, HH, 0, 0, 0);
    }

    prep_half<<<2048, 256>>>(hs, hs_h, (size_t)NB * TS * HH / 4);              // 5
    prep_wc<<<dim3(32, 64), dim3(32, 8)>>>(W_c, WcT_h);                        // 6

    // G2 (approx): score[b] = q_h[b] @ hs_h[b]^T  (single fp16), fp16 out
    {
        SegArgsH s{};
        s.a[0] = q_h;
        s.b[0] = hs_h;
        gemm_fp16<3,1><<<dim3(TS/128, TT/128, NB), 256, GEMM_SMEM>>>(          // 7
            s, nullptr, score, nullptr, nullptr, 1.0f,
            1024, TS, (long long)TT * HH, (long long)TS * HH, (long long)TT * TS);
    }

    // Fused: select + exact rescore (q . hs fp32) + softmax + gather -> c_h
    attend<<<NB * TT, 256>>>(score, q_h, q_l, hs, c_h, lens);                  // 8

    // G4: out = tanh([c|ht] @ W_c + b)  (single fp16, 2 segments over K=2048)
    {
        SegArgsH s{};
        s.a[0] = c_h;   s.a[1] = ht_h;
        s.b[0] = WcT_h; s.b[1] = WcT_h + 1024;
        gemm_fp16<2,2><<<dim3(OO/128, NB*TT/128, 1), 256, GEMM_SMEM>>>(        // 9
            s, out, nullptr, nullptr, bias, 1.0f,
            2048, OO, 0, 0, 0);
    }
}

// round 16
// speedup vs baseline: 1.2782x; 1.0217x over previous
#include <cuda_runtime.h>
#include <cuda_fp16.h>
#include <math.h>
#include <cstdint>

// Problem shape (fixed)
#define NB 16
#define TT 1024
#define TS 1024
#define HH 1024
#define OO 1024

// ---------------------------------------------------------------------------
// Scratch (device globals; no allocation). _h/_l = exact fp16 hi/lo pairs.
// ---------------------------------------------------------------------------
__device__ __half g_ht_h  [(size_t)NB * TT * HH];
__device__ __half g_ht_l  [(size_t)NB * TT * HH];
__device__ __half g_hs_h  [(size_t)NB * TS * HH];
__device__ __half g_Wa_h  [(size_t)HH * HH];        // Wa row-major, scaled by 32
__device__ __half g_Wa_l  [(size_t)HH * HH];        // Wa lo, scaled by 32
__device__ __half g_q_h   [(size_t)NB * TT * HH];   // q = ht @ Wa^T, hi
__device__ __half g_q_l   [(size_t)NB * TT * HH];   // q lo
__device__ __half g_c_h   [(size_t)NB * TT * HH];   // c fp16
__device__ __half g_WcT_h [(size_t)OO * 2 * HH];    // [O=1024][K=2048] fp16
__device__ __half g_score [(size_t)NB * TT * TS];   // approx scores fp16
__device__ int    g_lens  [NB];

// ---------------------------------------------------------------------------
// Helpers / PTX (base ISA only)
// ---------------------------------------------------------------------------
__device__ __forceinline__ uint32_t smem_u32(const void* p) {
    uint32_t a;
    asm("{ .reg .u64 t; cvta.to.shared.u64 t, %1; cvt.u32.u64 %0, t; }"
        : "=r"(a) : "l"(p));
    return a;
}

#define CPASYNC16(saddr, gaddr) \
    asm volatile("cp.async.cg.shared.global [%0], [%1], 16;" :: "r"(saddr), "l"(gaddr))

__device__ __forceinline__ void ldm4(uint32_t* r, uint32_t addr) {
    asm volatile("ldmatrix.sync.aligned.m8n8.x4.shared.b16 {%0,%1,%2,%3}, [%4];"
                 : "=r"(r[0]), "=r"(r[1]), "=r"(r[2]), "=r"(r[3]) : "r"(addr));
}
__device__ __forceinline__ void mma16h(float* c, const uint32_t* a, const uint32_t* b) {
    asm volatile(
        "mma.sync.aligned.m16n8k16.row.col.f32.f16.f16.f32 "
        "{%0,%1,%2,%3}, {%4,%5,%6,%7}, {%8,%9}, {%0,%1,%2,%3};"
        : "+f"(c[0]), "+f"(c[1]), "+f"(c[2]), "+f"(c[3])
        : "r"(a[0]), "r"(a[1]), "r"(a[2]), "r"(a[3]), "r"(b[0]), "r"(b[1]));
}

struct SegArgsH { const __half* a[3]; const __half* b[3]; };

static const int NSTG = 3;                       // 3 stages -> 2 CTAs/SM
static const int STAGE = 32768;                  // 16KB A + 16KB B
static const int GEMM_SMEM = 1024 + NSTG * STAGE;

// ---------------------------------------------------------------------------
// fp16 GEMM: C[M,N] = sum_seg A_seg[M,1024] * B_seg[N,1024]^T (fp16 in, fp32 acc)
// EPI: 1 fp16 split out (scaled), 2 tanh(x+bias) fp32, 3 fp16 single out
// Fill for stage kt+2 is issued AFTER k16=0's mma block (volatile asm keeps
// program order, so this overlaps the cp.async issue burst with tensor work).
// ---------------------------------------------------------------------------
template <int EPI, int NSEG>
__global__ __launch_bounds__(256, 2)
void gemm_fp16(const SegArgsH segs, float* __restrict__ Cf,
               __half* __restrict__ Ch, __half* __restrict__ Ch2,
               const float* __restrict__ bias, float oscale,
               int ldb, int ldc, long long sA, long long sB, long long sC)
{
    extern __shared__ char smem[];
    const uint32_t data = (smem_u32(smem) + 1023) & ~1023u;

    const int tid  = threadIdx.x;
    const int lane = tid & 31;
    const int warp = tid >> 5;
    const int wm = (warp >> 2) << 6;
    const int wn = (warp & 3) << 5;
    const int bm = blockIdx.y << 7;
    const int bn = blockIdx.x << 7;

    const long long zA = (long long)blockIdx.z * sA;
    const long long zB = (long long)blockIdx.z * sB;

    const int KT = NSEG * 16;            // k-steps of 64 fp16

    auto fill = [&](int kt, int s) {
        const int seg = kt >> 4;
        const int ka  = (kt & 15) << 6;
        const __half* Ap = segs.a[seg] + zA;
        const __half* Bp = segs.b[seg] + zB;
        const uint32_t sa = data + s * STAGE;
        const uint32_t sb = sa + 16384;
#pragma unroll
        for (int i = 0; i < 4; i++) {
            int c = tid + (i << 8);
            int row = c >> 3, ch = c & 7;
            const __half* g = Ap + (size_t)(bm + row) * 1024 + ka + (ch << 3);
            CPASYNC16(sa + (row << 7) + (((ch ^ (row & 7))) << 4), g);
        }
#pragma unroll
        for (int i = 0; i < 4; i++) {
            int c = tid + (i << 8);
            int row = c >> 3, ch = c & 7;
            const __half* g = Bp + (size_t)(bn + row) * ldb + ka + (ch << 3);
            CPASYNC16(sb + (row << 7) + (((ch ^ (row & 7))) << 4), g);
        }
    };

    fill(0, 0);
    asm volatile("cp.async.commit_group;" ::: "memory");
    fill(1, 1);
    asm volatile("cp.async.commit_group;" ::: "memory");

    float acc[4][4][4];
#pragma unroll
    for (int a = 0; a < 4; a++)
#pragma unroll
        for (int b = 0; b < 4; b++)
#pragma unroll
            for (int c = 0; c < 4; c++) acc[a][b][c] = 0.f;

    const int r8   = lane & 7;
    const int tile = lane >> 3;
    const int amo  = (tile & 1) << 3;
    const int akc  = tile >> 1;
    const int bno  = (lane >> 4) << 3;
    const int bkc  = (lane >> 3) & 1;

    int sc = 0;
    for (int kt = 0; kt < KT; kt++) {
        asm volatile("cp.async.wait_group 1;" ::: "memory");
        __syncthreads();

        const uint32_t Ab = data + sc * STAGE;
        const uint32_t Bs = Ab + 16384;
#pragma unroll
        for (int k16 = 0; k16 < 4; k16++) {
            uint32_t af[4][4], bf[2][4];
#pragma unroll
            for (int mt = 0; mt < 4; mt++) {
                int arow = wm + mt * 16 + r8 + amo;
                int achk = 2 * k16 + akc;
                ldm4(af[mt], Ab + (arow << 7) + (((achk ^ (arow & 7))) << 4));
            }
#pragma unroll
            for (int p = 0; p < 2; p++) {
                int brow = wn + (p << 4) + r8 + bno;
                int bchk = 2 * k16 + bkc;
                ldm4(bf[p], Bs + (brow << 7) + (((bchk ^ (brow & 7))) << 4));
            }
#pragma unroll
            for (int mt = 0; mt < 4; mt++)
#pragma unroll
                for (int nt = 0; nt < 4; nt++)
                    mma16h(acc[mt][nt], af[mt], &bf[nt >> 1][(nt & 1) << 1]);

            if (k16 == 0) {                      // overlap fill with k16=1..3
                int nf = kt + 2;
                int fs = (sc == 0) ? 2 : sc - 1;
                if (nf < KT) fill(nf, fs);
                asm volatile("cp.async.commit_group;" ::: "memory");
            }
        }
        sc = (sc == 2) ? 0 : sc + 1;
    }

    const int row0 = bm + wm + (lane >> 2);
    const int col0 = bn + wn + ((lane & 3) << 1);
#pragma unroll
    for (int mt = 0; mt < 4; mt++) {
#pragma unroll
        for (int nt = 0; nt < 4; nt++) {
            int col = col0 + nt * 8;
#pragma unroll
            for (int h = 0; h < 2; h++) {
                int row = row0 + mt * 16 + h * 8;
                float v0 = acc[mt][nt][2 * h + 0];
                float v1 = acc[mt][nt][2 * h + 1];
                size_t off = (size_t)blockIdx.z * sC + (size_t)row * ldc + col;
                if (EPI == 1) {                 // scaled fp16 split
                    v0 *= oscale; v1 *= oscale;
                    __half h0 = __float2half_rn(v0);
                    __half h1 = __float2half_rn(v1);
                    __half2 hv; hv.x = h0; hv.y = h1;
                    __half2 lv;
                    lv.x = __float2half_rn(v0 - __half2float(h0));
                    lv.y = __float2half_rn(v1 - __half2float(h1));
                    *(__half2*)(Ch + off)  = hv;
                    *(__half2*)(Ch2 + off) = lv;
                } else if (EPI == 2) {          // tanh + bias -> fp32
                    float2 o = {tanhf(v0 + bias[col]), tanhf(v1 + bias[col + 1])};
                    *(float2*)(Cf + off) = o;
                } else {                        // EPI == 3: fp16 single
                    __half2 hv;
                    hv.x = __float2half_rn(v0);
                    hv.y = __float2half_rn(v1);
                    *(__half2*)(Ch + off) = hv;
                }
            }
        }
    }
}

// ---------------------------------------------------------------------------
// Preprocessing
// ---------------------------------------------------------------------------
__global__ void prep_split(const float* __restrict__ in, __half* __restrict__ hh,
                           __half* __restrict__ hl, size_t n4)
{
    size_t i  = (size_t)blockIdx.x * blockDim.x + threadIdx.x;
    size_t st = (size_t)gridDim.x * blockDim.x;
    for (; i < n4; i += st) {
        float4 v = ((const float4*)in)[i];
        __half2 h0, h1, l0, l1;
        h0.x = __float2half_rn(v.x); l0.x = __float2half_rn(v.x - __half2float(h0.x));
        h0.y = __float2half_rn(v.y); l0.y = __float2half_rn(v.y - __half2float(h0.y));
        h1.x = __float2half_rn(v.z); l1.x = __float2half_rn(v.z - __half2float(h1.x));
        h1.y = __float2half_rn(v.w); l1.y = __float2half_rn(v.w - __half2float(h1.y));
        ((__half2*)hh)[2 * i]     = h0;
        ((__half2*)hh)[2 * i + 1] = h1;
        ((__half2*)hl)[2 * i]     = l0;
        ((__half2*)hl)[2 * i + 1] = l1;
    }
}

// Wa (no transpose): scaled-by-32 fp16 split, row-major pass-through
__global__ void prep_wa(const float* __restrict__ Wa, __half* __restrict__ hh,
                        __half* __restrict__ hl, size_t n4)
{
    size_t i  = (size_t)blockIdx.x * blockDim.x + threadIdx.x;
    size_t st = (size_t)gridDim.x * blockDim.x;
    for (; i < n4; i += st) {
        float4 v = ((const float4*)Wa)[i];
        v.x *= 32.0f; v.y *= 32.0f; v.z *= 32.0f; v.w *= 32.0f;
        __half2 h0, h1, l0, l1;
        h0.x = __float2half_rn(v.x); l0.x = __float2half_rn(v.x - __half2float(h0.x));
        h0.y = __float2half_rn(v.y); l0.y = __float2half_rn(v.y - __half2float(h0.y));
        h1.x = __float2half_rn(v.z); l1.x = __float2half_rn(v.z - __half2float(h1.x));
        h1.y = __float2half_rn(v.w); l1.y = __float2half_rn(v.w - __half2float(h1.y));
        ((__half2*)hh)[2 * i]     = h0;
        ((__half2*)hh)[2 * i + 1] = h1;
        ((__half2*)hl)[2 * i]     = l0;
        ((__half2*)hl)[2 * i + 1] = l1;
    }
}

__global__ void prep_half(const float* __restrict__ in, __half* __restrict__ out,
                          size_t n4)
{
    size_t i  = (size_t)blockIdx.x * blockDim.x + threadIdx.x;
    size_t st = (size_t)gridDim.x * blockDim.x;
    for (; i < n4; i += st) {
        float4 v = ((const float4*)in)[i];
        __half2 h0, h1;
        h0.x = __float2half_rn(v.x); h0.y = __float2half_rn(v.y);
        h1.x = __float2half_rn(v.z); h1.y = __float2half_rn(v.w);
        ((__half2*)out)[2 * i]     = h0;
        ((__half2*)out)[2 * i + 1] = h1;
    }
}

// Wc: dst[c][r] = fp16(src[r][c])  (transpose, [O][2048])
__global__ void prep_wc(const float* __restrict__ Wc, __half* __restrict__ WcT_h)
{
    __shared__ float t[32][33];
    int r0 = blockIdx.y << 5;
    int c0 = blockIdx.x << 5;
    int tx = threadIdx.x, ty = threadIdx.y;
#pragma unroll
    for (int i = 0; i < 32; i += 8)
        t[ty + i][tx] = Wc[(size_t)(r0 + ty + i) * 1024 + c0 + tx];
    __syncthreads();
#pragma unroll
    for (int i = 0; i < 32; i += 8) {
        size_t idx = (size_t)(c0 + ty + i) * 2048 + r0 + tx;
        WcT_h[idx] = __float2half_rn(t[tx][ty + i]);
    }
}

__global__ void lens_kernel(const int* __restrict__ source, int* __restrict__ lens)
{
    int b = blockIdx.x, tid = threadIdx.x;
    int cnt = 0;
    for (int s = tid; s < TS; s += blockDim.x)
        cnt += (source[(size_t)b * TS + s] != 0);
    __shared__ int red[256];
    red[tid] = cnt;
    __syncthreads();
    for (int s = 128; s > 0; s >>= 1) {
        if (tid < s) red[tid] += red[tid + s];
        __syncthreads();
    }
    if (tid == 0) lens[b] = red[0];
}

// ---------------------------------------------------------------------------
// Fused attend (block-per-row). C==1 fast path: softmax of one candidate is
// exactly 1, so rescore/softmax/q-load are skipped (bit-identical result).
// ---------------------------------------------------------------------------
#define CAP 64
__global__ __launch_bounds__(256)
void attend(const __half* __restrict__ score,
            const __half* __restrict__ q_h, const __half* __restrict__ q_l,
            const float* __restrict__ hs, __half* __restrict__ c_h,
            const int* __restrict__ lens)
{
    __shared__ float qrow[1024];
    __shared__ int   cand[CAP];
    __shared__ float exsc[CAP];
    __shared__ float wred[8];
    __shared__ int   ccnt;
    __shared__ float s_inv;

    const int row  = blockIdx.x;                 // 0 .. NB*TT-1
    const int b    = row >> 10;
    const int tid  = threadIdx.x;
    const int warp = tid >> 5, lane = tid & 31;
    const int len  = lens[b];
    const __half* srow = score + (size_t)row * TS;

    if (tid == 0) ccnt = 0;
    __syncthreads();                             // ccnt=0 visible before atomics

    // load 4 fp16 scores per thread; masked max via shfl + cross-warp smem
    __half2 p0 = ((const __half2*)srow)[2 * tid];
    __half2 p1 = ((const __half2*)srow)[2 * tid + 1];
    float v0 = __half2float(p0.x), v1 = __half2float(p0.y);
    float v2 = __half2float(p1.x), v3 = __half2float(p1.y);
    int base = tid << 2;
    float m = -1e30f;
    if (base + 0 < len) m = fmaxf(m, v0);
    if (base + 1 < len) m = fmaxf(m, v1);
    if (base + 2 < len) m = fmaxf(m, v2);
    if (base + 3 < len) m = fmaxf(m, v3);
#pragma unroll
    for (int s = 16; s > 0; s >>= 1)
        m = fmaxf(m, __shfl_xor_sync(0xffffffffu, m, s));
    if (lane == 0) wred[warp] = m;
    __syncthreads();
    if (warp == 0) {
        float mm = (lane < 8) ? wred[lane] : -1e30f;
#pragma unroll
        for (int s = 4; s > 0; s >>= 1)
            mm = fmaxf(mm, __shfl_xor_sync(0xffffffffu, mm, s));
        if (lane == 0) wred[0] = mm;
    }
    __syncthreads();
    const float thr = wred[0] - 10.0f;           // 9.2 cutoff + margin

    // select candidates (few -> atomics cheap)
    if (base + 0 < len && v0 >= thr) { int p = atomicAdd(&ccnt, 1); if (p < CAP) cand[p] = base + 0; }
    if (base + 1 < len && v1 >= thr) { int p = atomicAdd(&ccnt, 1); if (p < CAP) cand[p] = base + 1; }
    if (base + 2 < len && v2 >= thr) { int p = atomicAdd(&ccnt, 1); if (p < CAP) cand[p] = base + 2; }
    if (base + 3 < len && v3 >= thr) { int p = atomicAdd(&ccnt, 1); if (p < CAP) cand[p] = base + 3; }
    __syncthreads();
    const int C = (ccnt < CAP) ? ccnt : CAP;

    if (C == 1) {
        // fast path: weight is exactly 1 -> c = hs[cand0] (fp32 -> fp16)
        float4 h = ((const float4*)(hs + ((size_t)b * TS + cand[0]) * HH))[tid];
        __half2 o0, o1;
        o0.x = __float2half_rn(h.x); o0.y = __float2half_rn(h.y);
        o1.x = __float2half_rn(h.z); o1.y = __float2half_rn(h.w);
        ((__half2*)(c_h + (size_t)row * HH))[2 * tid]     = o0;
        ((__half2*)(c_h + (size_t)row * HH))[2 * tid + 1] = o1;
        return;
    }

    // q row (fp32 = h + l) into smem (only needed when C > 1)
    {
        __half2 qh0 = ((const __half2*)(q_h + (size_t)row * HH))[2 * tid];
        __half2 qh1 = ((const __half2*)(q_h + (size_t)row * HH))[2 * tid + 1];
        __half2 ql0 = ((const __half2*)(q_l + (size_t)row * HH))[2 * tid];
        __half2 ql1 = ((const __half2*)(q_l + (size_t)row * HH))[2 * tid + 1];
        float4 qv;
        qv.x = __half2float(qh0.x) + __half2float(ql0.x);
        qv.y = __half2float(qh0.y) + __half2float(ql0.y);
        qv.z = __half2float(qh1.x) + __half2float(ql1.x);
        qv.w = __half2float(qh1.y) + __half2float(ql1.y);
        ((float4*)qrow)[tid] = qv;
    }
    __syncthreads();

    // exact rescore: warp per candidate, fp32 hs rows (float4 loads)
    for (int ci = warp; ci < C; ci += 8) {
        const float4* hr = (const float4*)(hs + ((size_t)b * TS + cand[ci]) * HH);
        float acc = 0.f;
#pragma unroll
        for (int j = 0; j < 8; j++) {
            int k4 = (j << 5) + lane;
            float4 h4 = hr[k4];
            const float* q4 = &qrow[k4 << 2];
            acc = fmaf(q4[0], h4.x, acc);
            acc = fmaf(q4[1], h4.y, acc);
            acc = fmaf(q4[2], h4.z, acc);
            acc = fmaf(q4[3], h4.w, acc);
        }
#pragma unroll
        for (int s2 = 16; s2 > 0; s2 >>= 1)
            acc += __shfl_xor_sync(0xffffffffu, acc, s2);
        if (lane == 0) exsc[ci] = acc;
    }
    __syncthreads();

    // softmax over candidates: warp 0 lane-parallel
    if (warp == 0) {
        float mx = -1e30f;
        for (int i = lane; i < C; i += 32) mx = fmaxf(mx, exsc[i]);
#pragma unroll
        for (int s = 16; s > 0; s >>= 1)
            mx = fmaxf(mx, __shfl_xor_sync(0xffffffffu, mx, s));
        float sum = 0.f;
        for (int i = lane; i < C; i += 32) {
            float e = expf(exsc[i] - mx);
            exsc[i] = e;
            sum += e;
        }
#pragma unroll
        for (int s = 16; s > 0; s >>= 1)
            sum += __shfl_xor_sync(0xffffffffu, sum, s);
        if (lane == 0) s_inv = 1.0f / sum;
    }
    __syncthreads();
    const float inv = s_inv;

    // gather: c = sum a_k * hs[s_k]  (float4 accumulator; rows are L1-warm)
    float4 acc4 = {0.f, 0.f, 0.f, 0.f};
    for (int ci = 0; ci < C; ci++) {
        float wgt = exsc[ci] * inv;
        float4 h = ((const float4*)(hs + ((size_t)b * TS + cand[ci]) * HH))[tid];
        acc4.x = fmaf(wgt, h.x, acc4.x);
        acc4.y = fmaf(wgt, h.y, acc4.y);
        acc4.z = fmaf(wgt, h.z, acc4.z);
        acc4.w = fmaf(wgt, h.w, acc4.w);
    }
    __half2 o0, o1;
    o0.x = __float2half_rn(acc4.x); o0.y = __float2half_rn(acc4.y);
    o1.x = __float2half_rn(acc4.z); o1.y = __float2half_rn(acc4.w);
    ((__half2*)(c_h + (size_t)row * HH))[2 * tid]     = o0;
    ((__half2*)(c_h + (size_t)row * HH))[2 * tid + 1] = o1;
}

// ---------------------------------------------------------------------------
// Host launch
// ---------------------------------------------------------------------------
extern "C" void kernel_launch(void* const* d_in, const int* in_sizes, int n_in,
                              void* d_out, int out_size)
{
    const float* ht     = (const float*)d_in[0];
    const float* hs     = (const float*)d_in[1];
    const float* W_a    = (const float*)d_in[2];
    const float* W_c    = (const float*)d_in[3];
    const float* bias   = (const float*)d_in[4];
    const int*   source = (const int*)d_in[5];
    float* out = (float*)d_out;

    __half *ht_h, *ht_l, *hs_h, *Wa_h, *Wa_l, *q_h, *q_l, *c_h, *WcT_h, *score;
    int* lens;
    cudaGetSymbolAddress((void**)&ht_h,   g_ht_h);
    cudaGetSymbolAddress((void**)&ht_l,   g_ht_l);
    cudaGetSymbolAddress((void**)&hs_h,   g_hs_h);
    cudaGetSymbolAddress((void**)&Wa_h,   g_Wa_h);
    cudaGetSymbolAddress((void**)&Wa_l,   g_Wa_l);
    cudaGetSymbolAddress((void**)&q_h,    g_q_h);
    cudaGetSymbolAddress((void**)&q_l,    g_q_l);
    cudaGetSymbolAddress((void**)&c_h,    g_c_h);
    cudaGetSymbolAddress((void**)&WcT_h,  g_WcT_h);
    cudaGetSymbolAddress((void**)&score,  g_score);
    cudaGetSymbolAddress((void**)&lens,   g_lens);

    cudaFuncSetAttribute(gemm_fp16<1,3>, cudaFuncAttributeMaxDynamicSharedMemorySize, GEMM_SMEM);
    cudaFuncSetAttribute(gemm_fp16<3,1>, cudaFuncAttributeMaxDynamicSharedMemorySize, GEMM_SMEM);
    cudaFuncSetAttribute(gemm_fp16<2,2>, cudaFuncAttributeMaxDynamicSharedMemorySize, GEMM_SMEM);

    // Preprocess (G1 stays launch #4 for ncu)
    prep_wa<<<256, 256>>>(W_a, Wa_h, Wa_l, (size_t)HH * HH / 4);               // 1
    prep_split<<<2048, 256>>>(ht, ht_h, ht_l, (size_t)NB * TT * HH / 4);       // 2
    lens_kernel<<<NB, 256>>>(source, lens);                                    // 3

    // G1: q = ht @ Wa^T  (3xFP16, Wa scaled by 32) -> q_h, q_l (x 1/32)
    {
        SegArgsH s{};
        s.a[0] = ht_h; s.a[1] = ht_l; s.a[2] = ht_h;
        s.b[0] = Wa_h; s.b[1] = Wa_h; s.b[2] = Wa_l;
        gemm_fp16<1,3><<<dim3(HH/128, NB*TT/128, 1), 256, GEMM_SMEM>>>(        // 4
            s, nullptr, q_h, q_l, nullptr, 1.0f / 32.0f,
            1024, HH, 0, 0, 0);
    }

    prep_half<<<2048, 256>>>(hs, hs_h, (size_t)NB * TS * HH / 4);              // 5
    prep_wc<<<dim3(32, 64), dim3(32, 8)>>>(W_c, WcT_h);                        // 6

    // G2 (approx): score[b] = q_h[b] @ hs_h[b]^T  (single fp16), fp16 out
    {
        SegArgsH s{};
        s.a[0] = q_h;
        s.b[0] = hs_h;
        gemm_fp16<3,1><<<dim3(TS/128, TT/128, NB), 256, GEMM_SMEM>>>(          // 7
            s, nullptr, score, nullptr, nullptr, 1.0f,
            1024, TS, (long long)TT * HH, (long long)TS * HH, (long long)TT * TS);
    }

    // Fused: select + exact rescore (q . hs fp32) + softmax + gather -> c_h
    attend<<<NB * TT, 256>>>(score, q_h, q_l, hs, c_h, lens);                  // 8

    // G4: out = tanh([c|ht] @ W_c + b)  (single fp16, 2 segments over K=2048)
    {
        SegArgsH s{};
        s.a[0] = c_h;   s.a[1] = ht_h;
        s.b[0] = WcT_h; s.b[1] = WcT_h + 1024;
        gemm_fp16<2,2><<<dim3(OO/128, NB*TT/128, 1), 256, GEMM_SMEM>>>(        // 9
            s, out, nullptr, nullptr, bias, 1.0f,
            2048, OO, 0, 0, 0);
    }
}

// round 17
// speedup vs baseline: 1.4393x; 1.1260x over previous
#include <cuda_runtime.h>
#include <cuda_fp16.h>
#include <math.h>
#include <cstdint>

// Problem shape (fixed)
#define NB 16
#define TT 1024
#define TS 1024
#define HH 1024
#define OO 1024

// ---------------------------------------------------------------------------
// Scratch (device globals; no allocation). _h/_l = exact fp16 hi/lo pairs.
// ---------------------------------------------------------------------------
__device__ __half g_ht_h  [(size_t)NB * TT * HH];
__device__ __half g_ht_l  [(size_t)NB * TT * HH];
__device__ __half g_hs_h  [(size_t)NB * TS * HH];
__device__ __half g_Wa_h  [(size_t)HH * HH];        // Wa row-major, scaled by 32
__device__ __half g_q_h   [(size_t)NB * TT * HH];   // q = ht @ Wa^T, hi
__device__ __half g_q_l   [(size_t)NB * TT * HH];   // q lo
__device__ __half g_c_h   [(size_t)NB * TT * HH];   // c fp16
__device__ __half g_WcT_h [(size_t)OO * 2 * HH];    // [O=1024][K=2048] fp16
__device__ __half g_score [(size_t)NB * TT * TS];   // approx scores fp16
__device__ int    g_lens  [NB];

// ---------------------------------------------------------------------------
// Helpers / PTX (base ISA only)
// ---------------------------------------------------------------------------
__device__ __forceinline__ uint32_t smem_u32(const void* p) {
    uint32_t a;
    asm("{ .reg .u64 t; cvta.to.shared.u64 t, %1; cvt.u32.u64 %0, t; }"
        : "=r"(a) : "l"(p));
    return a;
}

#define CPASYNC16(saddr, gaddr) \
    asm volatile("cp.async.cg.shared.global [%0], [%1], 16;" :: "r"(saddr), "l"(gaddr))

__device__ __forceinline__ void ldm4(uint32_t* r, uint32_t addr) {
    asm volatile("ldmatrix.sync.aligned.m8n8.x4.shared.b16 {%0,%1,%2,%3}, [%4];"
                 : "=r"(r[0]), "=r"(r[1]), "=r"(r[2]), "=r"(r[3]) : "r"(addr));
}
__device__ __forceinline__ void mma16h(float* c, const uint32_t* a, const uint32_t* b) {
    asm volatile(
        "mma.sync.aligned.m16n8k16.row.col.f32.f16.f16.f32 "
        "{%0,%1,%2,%3}, {%4,%5,%6,%7}, {%8,%9}, {%0,%1,%2,%3};"
        : "+f"(c[0]), "+f"(c[1]), "+f"(c[2]), "+f"(c[3])
        : "r"(a[0]), "r"(a[1]), "r"(a[2]), "r"(a[3]), "r"(b[0]), "r"(b[1]));
}

struct SegArgsH { const __half* a[3]; const __half* b[3]; };

static const int NSTG = 3;                       // 3 stages -> 2 CTAs/SM
static const int STAGE = 32768;                  // 16KB A + 16KB B
static const int GEMM_SMEM = 1024 + NSTG * STAGE;

// ---------------------------------------------------------------------------
// fp16 GEMM: C[M,N] = sum_seg A_seg[M,1024] * B_seg[N,1024]^T (fp16 in, fp32 acc)
// EPI: 1 fp16 split out (scaled), 2 tanh(x+bias) fp32, 3 fp16 single out
// Fill for stage kt+2 issued after k16=0's mma block (overlaps with compute).
// ---------------------------------------------------------------------------
template <int EPI, int NSEG>
__global__ __launch_bounds__(256, 2)
void gemm_fp16(const SegArgsH segs, float* __restrict__ Cf,
               __half* __restrict__ Ch, __half* __restrict__ Ch2,
               const float* __restrict__ bias, float oscale,
               int ldb, int ldc, long long sA, long long sB, long long sC)
{
    extern __shared__ char smem[];
    const uint32_t data = (smem_u32(smem) + 1023) & ~1023u;

    const int tid  = threadIdx.x;
    const int lane = tid & 31;
    const int warp = tid >> 5;
    const int wm = (warp >> 2) << 6;
    const int wn = (warp & 3) << 5;
    const int bm = blockIdx.y << 7;
    const int bn = blockIdx.x << 7;

    const long long zA = (long long)blockIdx.z * sA;
    const long long zB = (long long)blockIdx.z * sB;

    const int KT = NSEG * 16;            // k-steps of 64 fp16

    auto fill = [&](int kt, int s) {
        const int seg = kt >> 4;
        const int ka  = (kt & 15) << 6;
        const __half* Ap = segs.a[seg] + zA;
        const __half* Bp = segs.b[seg] + zB;
        const uint32_t sa = data + s * STAGE;
        const uint32_t sb = sa + 16384;
#pragma unroll
        for (int i = 0; i < 4; i++) {
            int c = tid + (i << 8);
            int row = c >> 3, ch = c & 7;
            const __half* g = Ap + (size_t)(bm + row) * 1024 + ka + (ch << 3);
            CPASYNC16(sa + (row << 7) + (((ch ^ (row & 7))) << 4), g);
        }
#pragma unroll
        for (int i = 0; i < 4; i++) {
            int c = tid + (i << 8);
            int row = c >> 3, ch = c & 7;
            const __half* g = Bp + (size_t)(bn + row) * ldb + ka + (ch << 3);
            CPASYNC16(sb + (row << 7) + (((ch ^ (row & 7))) << 4), g);
        }
    };

    fill(0, 0);
    asm volatile("cp.async.commit_group;" ::: "memory");
    fill(1, 1);
    asm volatile("cp.async.commit_group;" ::: "memory");

    float acc[4][4][4];
#pragma unroll
    for (int a = 0; a < 4; a++)
#pragma unroll
        for (int b = 0; b < 4; b++)
#pragma unroll
            for (int c = 0; c < 4; c++) acc[a][b][c] = 0.f;

    const int r8   = lane & 7;
    const int tile = lane >> 3;
    const int amo  = (tile & 1) << 3;
    const int akc  = tile >> 1;
    const int bno  = (lane >> 4) << 3;
    const int bkc  = (lane >> 3) & 1;

    int sc = 0;
    for (int kt = 0; kt < KT; kt++) {
        asm volatile("cp.async.wait_group 1;" ::: "memory");
        __syncthreads();

        const uint32_t Ab = data + sc * STAGE;
        const uint32_t Bs = Ab + 16384;
#pragma unroll
        for (int k16 = 0; k16 < 4; k16++) {
            uint32_t af[4][4], bf[2][4];
#pragma unroll
            for (int mt = 0; mt < 4; mt++) {
                int arow = wm + mt * 16 + r8 + amo;
                int achk = 2 * k16 + akc;
                ldm4(af[mt], Ab + (arow << 7) + (((achk ^ (arow & 7))) << 4));
            }
#pragma unroll
            for (int p = 0; p < 2; p++) {
                int brow = wn + (p << 4) + r8 + bno;
                int bchk = 2 * k16 + bkc;
                ldm4(bf[p], Bs + (brow << 7) + (((bchk ^ (brow & 7))) << 4));
            }
#pragma unroll
            for (int mt = 0; mt < 4; mt++)
#pragma unroll
                for (int nt = 0; nt < 4; nt++)
                    mma16h(acc[mt][nt], af[mt], &bf[nt >> 1][(nt & 1) << 1]);

            if (k16 == 0) {                      // overlap fill with k16=1..3
                int nf = kt + 2;
                int fs = (sc == 0) ? 2 : sc - 1;
                if (nf < KT) fill(nf, fs);
                asm volatile("cp.async.commit_group;" ::: "memory");
            }
        }
        sc = (sc == 2) ? 0 : sc + 1;
    }

    const int row0 = bm + wm + (lane >> 2);
    const int col0 = bn + wn + ((lane & 3) << 1);
#pragma unroll
    for (int mt = 0; mt < 4; mt++) {
#pragma unroll
        for (int nt = 0; nt < 4; nt++) {
            int col = col0 + nt * 8;
#pragma unroll
            for (int h = 0; h < 2; h++) {
                int row = row0 + mt * 16 + h * 8;
                float v0 = acc[mt][nt][2 * h + 0];
                float v1 = acc[mt][nt][2 * h + 1];
                size_t off = (size_t)blockIdx.z * sC + (size_t)row * ldc + col;
                if (EPI == 1) {                 // scaled fp16 split
                    v0 *= oscale; v1 *= oscale;
                    __half h0 = __float2half_rn(v0);
                    __half h1 = __float2half_rn(v1);
                    __half2 hv; hv.x = h0; hv.y = h1;
                    __half2 lv;
                    lv.x = __float2half_rn(v0 - __half2float(h0));
                    lv.y = __float2half_rn(v1 - __half2float(h1));
                    *(__half2*)(Ch + off)  = hv;
                    *(__half2*)(Ch2 + off) = lv;
                } else if (EPI == 2) {          // tanh + bias -> fp32
                    float2 o = {tanhf(v0 + bias[col]), tanhf(v1 + bias[col + 1])};
                    *(float2*)(Cf + off) = o;
                } else {                        // EPI == 3: fp16 single
                    __half2 hv;
                    hv.x = __float2half_rn(v0);
                    hv.y = __float2half_rn(v1);
                    *(__half2*)(Ch + off) = hv;
                }
            }
        }
    }
}

// ---------------------------------------------------------------------------
// Preprocessing
// ---------------------------------------------------------------------------
__global__ void prep_split(const float* __restrict__ in, __half* __restrict__ hh,
                           __half* __restrict__ hl, size_t n4)
{
    size_t i  = (size_t)blockIdx.x * blockDim.x + threadIdx.x;
    size_t st = (size_t)gridDim.x * blockDim.x;
    for (; i < n4; i += st) {
        float4 v = ((const float4*)in)[i];
        __half2 h0, h1, l0, l1;
        h0.x = __float2half_rn(v.x); l0.x = __float2half_rn(v.x - __half2float(h0.x));
        h0.y = __float2half_rn(v.y); l0.y = __float2half_rn(v.y - __half2float(h0.y));
        h1.x = __float2half_rn(v.z); l1.x = __float2half_rn(v.z - __half2float(h1.x));
        h1.y = __float2half_rn(v.w); l1.y = __float2half_rn(v.w - __half2float(h1.y));
        ((__half2*)hh)[2 * i]     = h0;
        ((__half2*)hh)[2 * i + 1] = h1;
        ((__half2*)hl)[2 * i]     = l0;
        ((__half2*)hl)[2 * i + 1] = l1;
    }
}

// Wa (no transpose): scaled-by-32 fp16 hi only
__global__ void prep_wa(const float* __restrict__ Wa, __half* __restrict__ hh,
                        size_t n4)
{
    size_t i  = (size_t)blockIdx.x * blockDim.x + threadIdx.x;
    size_t st = (size_t)gridDim.x * blockDim.x;
    for (; i < n4; i += st) {
        float4 v = ((const float4*)Wa)[i];
        __half2 h0, h1;
        h0.x = __float2half_rn(32.0f * v.x); h0.y = __float2half_rn(32.0f * v.y);
        h1.x = __float2half_rn(32.0f * v.z); h1.y = __float2half_rn(32.0f * v.w);
        ((__half2*)hh)[2 * i]     = h0;
        ((__half2*)hh)[2 * i + 1] = h1;
    }
}

__global__ void prep_half(const float* __restrict__ in, __half* __restrict__ out,
                          size_t n4)
{
    size_t i  = (size_t)blockIdx.x * blockDim.x + threadIdx.x;
    size_t st = (size_t)gridDim.x * blockDim.x;
    for (; i < n4; i += st) {
        float4 v = ((const float4*)in)[i];
        __half2 h0, h1;
        h0.x = __float2half_rn(v.x); h0.y = __float2half_rn(v.y);
        h1.x = __float2half_rn(v.z); h1.y = __float2half_rn(v.w);
        ((__half2*)out)[2 * i]     = h0;
        ((__half2*)out)[2 * i + 1] = h1;
    }
}

// Wc: dst[c][r] = fp16(src[r][c])  (transpose, [O][2048])
__global__ void prep_wc(const float* __restrict__ Wc, __half* __restrict__ WcT_h)
{
    __shared__ float t[32][33];
    int r0 = blockIdx.y << 5;
    int c0 = blockIdx.x << 5;
    int tx = threadIdx.x, ty = threadIdx.y;
#pragma unroll
    for (int i = 0; i < 32; i += 8)
        t[ty + i][tx] = Wc[(size_t)(r0 + ty + i) * 1024 + c0 + tx];
    __syncthreads();
#pragma unroll
    for (int i = 0; i < 32; i += 8) {
        size_t idx = (size_t)(c0 + ty + i) * 2048 + r0 + tx;
        WcT_h[idx] = __float2half_rn(t[tx][ty + i]);
    }
}

__global__ void lens_kernel(const int* __restrict__ source, int* __restrict__ lens)
{
    int b = blockIdx.x, tid = threadIdx.x;
    int cnt = 0;
    for (int s = tid; s < TS; s += blockDim.x)
        cnt += (source[(size_t)b * TS + s] != 0);
    __shared__ int red[256];
    red[tid] = cnt;
    __syncthreads();
    for (int s = 128; s > 0; s >>= 1) {
        if (tid < s) red[tid] += red[tid + s];
        __syncthreads();
    }
    if (tid == 0) lens[b] = red[0];
}

// ---------------------------------------------------------------------------
// Fused attend (block-per-row). C==1 fast path (weight exactly 1).
// ---------------------------------------------------------------------------
#define CAP 64
__global__ __launch_bounds__(256)
void attend(const __half* __restrict__ score,
            const __half* __restrict__ q_h, const __half* __restrict__ q_l,
            const float* __restrict__ hs, __half* __restrict__ c_h,
            const int* __restrict__ lens)
{
    __shared__ float qrow[1024];
    __shared__ int   cand[CAP];
    __shared__ float exsc[CAP];
    __shared__ float wred[8];
    __shared__ int   ccnt;
    __shared__ float s_inv;

    const int row  = blockIdx.x;                 // 0 .. NB*TT-1
    const int b    = row >> 10;
    const int tid  = threadIdx.x;
    const int warp = tid >> 5, lane = tid & 31;
    const int len  = lens[b];
    const __half* srow = score + (size_t)row * TS;

    if (tid == 0) ccnt = 0;
    __syncthreads();

    __half2 p0 = ((const __half2*)srow)[2 * tid];
    __half2 p1 = ((const __half2*)srow)[2 * tid + 1];
    float v0 = __half2float(p0.x), v1 = __half2float(p0.y);
    float v2 = __half2float(p1.x), v3 = __half2float(p1.y);
    int base = tid << 2;
    float m = -1e30f;
    if (base + 0 < len) m = fmaxf(m, v0);
    if (base + 1 < len) m = fmaxf(m, v1);
    if (base + 2 < len) m = fmaxf(m, v2);
    if (base + 3 < len) m = fmaxf(m, v3);
#pragma unroll
    for (int s = 16; s > 0; s >>= 1)
        m = fmaxf(m, __shfl_xor_sync(0xffffffffu, m, s));
    if (lane == 0) wred[warp] = m;
    __syncthreads();
    if (warp == 0) {
        float mm = (lane < 8) ? wred[lane] : -1e30f;
#pragma unroll
        for (int s = 4; s > 0; s >>= 1)
            mm = fmaxf(mm, __shfl_xor_sync(0xffffffffu, mm, s));
        if (lane == 0) wred[0] = mm;
    }
    __syncthreads();
    const float thr = wred[0] - 10.0f;           // 9.2 cutoff + margin

    if (base + 0 < len && v0 >= thr) { int p = atomicAdd(&ccnt, 1); if (p < CAP) cand[p] = base + 0; }
    if (base + 1 < len && v1 >= thr) { int p = atomicAdd(&ccnt, 1); if (p < CAP) cand[p] = base + 1; }
    if (base + 2 < len && v2 >= thr) { int p = atomicAdd(&ccnt, 1); if (p < CAP) cand[p] = base + 2; }
    if (base + 3 < len && v3 >= thr) { int p = atomicAdd(&ccnt, 1); if (p < CAP) cand[p] = base + 3; }
    __syncthreads();
    const int C = (ccnt < CAP) ? ccnt : CAP;

    if (C == 1) {
        float4 h = ((const float4*)(hs + ((size_t)b * TS + cand[0]) * HH))[tid];
        __half2 o0, o1;
        o0.x = __float2half_rn(h.x); o0.y = __float2half_rn(h.y);
        o1.x = __float2half_rn(h.z); o1.y = __float2half_rn(h.w);
        ((__half2*)(c_h + (size_t)row * HH))[2 * tid]     = o0;
        ((__half2*)(c_h + (size_t)row * HH))[2 * tid + 1] = o1;
        return;
    }

    // q row (fp32 = h + l) into smem
    {
        __half2 qh0 = ((const __half2*)(q_h + (size_t)row * HH))[2 * tid];
        __half2 qh1 = ((const __half2*)(q_h + (size_t)row * HH))[2 * tid + 1];
        __half2 ql0 = ((const __half2*)(q_l + (size_t)row * HH))[2 * tid];
        __half2 ql1 = ((const __half2*)(q_l + (size_t)row * HH))[2 * tid + 1];
        float4 qv;
        qv.x = __half2float(qh0.x) + __half2float(ql0.x);
        qv.y = __half2float(qh0.y) + __half2float(ql0.y);
        qv.z = __half2float(qh1.x) + __half2float(ql1.x);
        qv.w = __half2float(qh1.y) + __half2float(ql1.y);
        ((float4*)qrow)[tid] = qv;
    }
    __syncthreads();

    // exact rescore: warp per candidate, fp32 hs rows
    for (int ci = warp; ci < C; ci += 8) {
        const float4* hr = (const float4*)(hs + ((size_t)b * TS + cand[ci]) * HH);
        float acc = 0.f;
#pragma unroll
        for (int j = 0; j < 8; j++) {
            int k4 = (j << 5) + lane;
            float4 h4 = hr[k4];
            const float* q4 = &qrow[k4 << 2];
            acc = fmaf(q4[0], h4.x, acc);
            acc = fmaf(q4[1], h4.y, acc);
            acc = fmaf(q4[2], h4.z, acc);
            acc = fmaf(q4[3], h4.w, acc);
        }
#pragma unroll
        for (int s2 = 16; s2 > 0; s2 >>= 1)
            acc += __shfl_xor_sync(0xffffffffu, acc, s2);
        if (lane == 0) exsc[ci] = acc;
    }
    __syncthreads();

    // softmax over candidates: warp 0 lane-parallel
    if (warp == 0) {
        float mx = -1e30f;
        for (int i = lane; i < C; i += 32) mx = fmaxf(mx, exsc[i]);
#pragma unroll
        for (int s = 16; s > 0; s >>= 1)
            mx = fmaxf(mx, __shfl_xor_sync(0xffffffffu, mx, s));
        float sum = 0.f;
        for (int i = lane; i < C; i += 32) {
            float e = expf(exsc[i] - mx);
            exsc[i] = e;
            sum += e;
        }
#pragma unroll
        for (int s = 16; s > 0; s >>= 1)
            sum += __shfl_xor_sync(0xffffffffu, sum, s);
        if (lane == 0) s_inv = 1.0f / sum;
    }
    __syncthreads();
    const float inv = s_inv;

    // gather (rows L1-warm from rescore)
    float4 acc4 = {0.f, 0.f, 0.f, 0.f};
    for (int ci = 0; ci < C; ci++) {
        float wgt = exsc[ci] * inv;
        float4 h = ((const float4*)(hs + ((size_t)b * TS + cand[ci]) * HH))[tid];
        acc4.x = fmaf(wgt, h.x, acc4.x);
        acc4.y = fmaf(wgt, h.y, acc4.y);
        acc4.z = fmaf(wgt, h.z, acc4.z);
        acc4.w = fmaf(wgt, h.w, acc4.w);
    }
    __half2 o0, o1;
    o0.x = __float2half_rn(acc4.x); o0.y = __float2half_rn(acc4.y);
    o1.x = __float2half_rn(acc4.z); o1.y = __float2half_rn(acc4.w);
    ((__half2*)(c_h + (size_t)row * HH))[2 * tid]     = o0;
    ((__half2*)(c_h + (size_t)row * HH))[2 * tid + 1] = o1;
}

// ---------------------------------------------------------------------------
// Host launch
// ---------------------------------------------------------------------------
extern "C" void kernel_launch(void* const* d_in, const int* in_sizes, int n_in,
                              void* d_out, int out_size)
{
    const float* ht     = (const float*)d_in[0];
    const float* hs     = (const float*)d_in[1];
    const float* W_a    = (const float*)d_in[2];
    const float* W_c    = (const float*)d_in[3];
    const float* bias   = (const float*)d_in[4];
    const int*   source = (const int*)d_in[5];
    float* out = (float*)d_out;

    __half *ht_h, *ht_l, *hs_h, *Wa_h, *q_h, *q_l, *c_h, *WcT_h, *score;
    int* lens;
    cudaGetSymbolAddress((void**)&ht_h,   g_ht_h);
    cudaGetSymbolAddress((void**)&ht_l,   g_ht_l);
    cudaGetSymbolAddress((void**)&hs_h,   g_hs_h);
    cudaGetSymbolAddress((void**)&Wa_h,   g_Wa_h);
    cudaGetSymbolAddress((void**)&q_h,    g_q_h);
    cudaGetSymbolAddress((void**)&q_l,    g_q_l);
    cudaGetSymbolAddress((void**)&c_h,    g_c_h);
    cudaGetSymbolAddress((void**)&WcT_h,  g_WcT_h);
    cudaGetSymbolAddress((void**)&score,  g_score);
    cudaGetSymbolAddress((void**)&lens,   g_lens);

    cudaFuncSetAttribute(gemm_fp16<1,2>, cudaFuncAttributeMaxDynamicSharedMemorySize, GEMM_SMEM);
    cudaFuncSetAttribute(gemm_fp16<3,1>, cudaFuncAttributeMaxDynamicSharedMemorySize, GEMM_SMEM);
    cudaFuncSetAttribute(gemm_fp16<2,2>, cudaFuncAttributeMaxDynamicSharedMemorySize, GEMM_SMEM);

    // Preprocess (G1 stays launch #4 for ncu)
    prep_wa<<<256, 256>>>(W_a, Wa_h, (size_t)HH * HH / 4);                     // 1
    prep_split<<<2048, 256>>>(ht, ht_h, ht_l, (size_t)NB * TT * HH / 4);       // 2
    lens_kernel<<<NB, 256>>>(source, lens);                                    // 3

    // G1: q = ht @ Wa^T  (2xFP16: hi.hi + lo.hi; Wa scaled by 32)
    {
        SegArgsH s{};
        s.a[0] = ht_h; s.a[1] = ht_l;
        s.b[0] = Wa_h; s.b[1] = Wa_h;
        gemm_fp16<1,2><<<dim3(HH/128, NB*TT/128, 1), 256, GEMM_SMEM>>>(        // 4
            s, nullptr, q_h, q_l, nullptr, 1.0f / 32.0f,
            1024, HH, 0, 0, 0);
    }

    prep_half<<<2048, 256>>>(hs, hs_h, (size_t)NB * TS * HH / 4);              // 5
    prep_wc<<<dim3(32, 64), dim3(32, 8)>>>(W_c, WcT_h);                        // 6

    // G2 (approx): score[b] = q_h[b] @ hs_h[b]^T  (single fp16), fp16 out
    {
        SegArgsH s{};
        s.a[0] = q_h;
        s.b[0] = hs_h;
        gemm_fp16<3,1><<<dim3(TS/128, TT/128, NB), 256, GEMM_SMEM>>>(          // 7
            s, nullptr, score, nullptr, nullptr, 1.0f,
            1024, TS, (long long)TT * HH, (long long)TS * HH, (long long)TT * TS);
    }

    // Fused: select + exact rescore (q . hs fp32) + softmax + gather -> c_h
    attend<<<NB * TT, 256>>>(score, q_h, q_l, hs, c_h, lens);                  // 8

    // G4: out = tanh([c|ht] @ W_c + b)  (single fp16, 2 segments over K=2048)
    {
        SegArgsH s{};
        s.a[0] = c_h;   s.a[1] = ht_h;
        s.b[0] = WcT_h; s.b[1] = WcT_h + 1024;
        gemm_fp16<2,2><<<dim3(OO/128, NB*TT/128, 1), 256, GEMM_SMEM>>>(        // 9
            s, out, nullptr, nullptr, bias, 1.0f,
            2048, OO, 0, 0, 0);
    }
}